// round 12
// baseline (speedup 1.0000x reference)
#include <cuda_runtime.h>
#include <cuda_fp16.h>
#include <math.h>
#include <stdint.h>

// Problem constants
#define B_   16
#define C_   384
#define N_   1024
#define NH   8
#define HD   48
#define HID  1536
#define M_   (B_*N_)     // 16384 tokens
#define QKVC (3*C_)      // 1152

// ---------------------------------------------------------------------------
// Scratch
// ---------------------------------------------------------------------------
__device__ float  g_x2 [M_*C_];
__device__ __half g_h16 [M_*C_];
__device__ __half g_qkv16[M_*QKVC];
__device__ __half g_att16[M_*C_];
__device__ __half g_mid16[M_*HID];
__device__ __half g_w16[1769472];
#define W_QKV 0
#define W_PROJ 442368
#define W_FC1 589824
#define W_FC2 1179648

// ---------------------------------------------------------------------------
// Helpers
// ---------------------------------------------------------------------------
__device__ __forceinline__ uint32_t smem_u32(const void* p) {
    uint32_t a;
    asm("{ .reg .u64 t; cvta.to.shared.u64 t, %1; cvt.u32.u64 %0, t; }"
        : "=r"(a) : "l"(p));
    return a;
}
#define SW64(o)  ((o) ^ (((o) >> 3) & 0x30))
#define SW128(o) ((o) ^ (((o) >> 3) & 0x70))

__device__ __forceinline__ void ldsm4(uint32_t addr, uint32_t r[4]) {
    asm volatile("ldmatrix.sync.aligned.m8n8.x4.shared.b16 {%0,%1,%2,%3}, [%4];"
                 : "=r"(r[0]), "=r"(r[1]), "=r"(r[2]), "=r"(r[3]) : "r"(addr));
}
__device__ __forceinline__ void ldsm4t(uint32_t addr, uint32_t r[4]) {
    asm volatile("ldmatrix.sync.aligned.m8n8.x4.trans.shared.b16 {%0,%1,%2,%3}, [%4];"
                 : "=r"(r[0]), "=r"(r[1]), "=r"(r[2]), "=r"(r[3]) : "r"(addr));
}
__device__ __forceinline__ void mmaf16(float* c, const uint32_t* a,
                                       uint32_t b0, uint32_t b1) {
    asm volatile("mma.sync.aligned.m16n8k16.row.col.f32.f16.f16.f32 "
                 "{%0,%1,%2,%3}, {%4,%5,%6,%7}, {%8,%9}, {%0,%1,%2,%3};"
                 : "+f"(c[0]), "+f"(c[1]), "+f"(c[2]), "+f"(c[3])
                 : "r"(a[0]), "r"(a[1]), "r"(a[2]), "r"(a[3]), "r"(b0), "r"(b1));
}
__device__ __forceinline__ void mmaf16v(float* c, uint32_t a0, uint32_t a1,
                                        uint32_t a2, uint32_t a3,
                                        uint32_t b0, uint32_t b1) {
    asm volatile("mma.sync.aligned.m16n8k16.row.col.f32.f16.f16.f32 "
                 "{%0,%1,%2,%3}, {%4,%5,%6,%7}, {%8,%9}, {%0,%1,%2,%3};"
                 : "+f"(c[0]), "+f"(c[1]), "+f"(c[2]), "+f"(c[3])
                 : "r"(a0), "r"(a1), "r"(a2), "r"(a3), "r"(b0), "r"(b1));
}
__device__ __forceinline__ void cpasync16(uint32_t s, const void* g) {
    asm volatile("cp.async.cg.shared.global [%0], [%1], 16;" :: "r"(s), "l"(g));
}
__device__ __forceinline__ uint32_t packh2(float x, float y) {
    __half2 t = __floats2half2_rn(x, y);
    return *(uint32_t*)&t;
}
__device__ __forceinline__ uint32_t h2ex2(uint32_t x) {
    uint32_t r;
    asm("ex2.approx.f16x2 %0, %1;" : "=r"(r) : "r"(x));
    return r;
}
__device__ __forceinline__ uint32_t h2mul(uint32_t a, uint32_t b) {
    uint32_t r;
    asm("mul.f16x2 %0, %1, %2;" : "=r"(r) : "r"(a), "r"(b));
    return r;
}

// ---------------------------------------------------------------------------
// All weights fp32 -> fp16 in one launch
// ---------------------------------------------------------------------------
__global__ void cvt_all(const float* __restrict__ qkvw, const float* __restrict__ projw,
                        const float* __restrict__ fc1w, const float* __restrict__ fc2w,
                        __half* __restrict__ w16) {
    int i = blockIdx.x * 256 + threadIdx.x;   // 0 .. 442367
    const float* s;
    __half* d;
    if (i < 110592)      { s = qkvw;  d = w16 + W_QKV;  }
    else if (i < 147456) { s = projw; d = w16 + W_PROJ; i -= 110592; }
    else if (i < 294912) { s = fc1w;  d = w16 + W_FC1;  i -= 147456; }
    else                 { s = fc2w;  d = w16 + W_FC2;  i -= 294912; }
    float4 v = ((const float4*)s)[i];
    __half2* dp = (__half2*)d;
    dp[2 * i]     = __floats2half2_rn(v.x, v.y);
    dp[2 * i + 1] = __floats2half2_rn(v.z, v.w);
}

// ---------------------------------------------------------------------------
// Fused transpose + LayerNorm: x (B,C,N) fp32 -> h16 (B,N,C) fp16
// ---------------------------------------------------------------------------
__global__ __launch_bounds__(256)
void transln_k(const float* __restrict__ x, const float* __restrict__ w,
               const float* __restrict__ bias, __half* __restrict__ Y) {
    __shared__ float fs[384 * 17];
    __shared__ float ps[256], pq[256];
    __shared__ float mrow[16], rrow[16];
    const int b = blockIdx.y, n0 = blockIdx.x * 16;
    const int tok = threadIdx.x & 15, c0 = threadIdx.x >> 4;
    const float* xb = x + (size_t)b * C_ * N_ + n0;
    float s = 0.0f, q = 0.0f;
    #pragma unroll
    for (int i = 0; i < 24; i++) {
        int c = c0 + i * 16;
        float v = xb[(size_t)c * N_ + tok];
        s += v; q += v * v;
        fs[c * 17 + tok] = v;
    }
    ps[c0 * 16 + tok] = s;
    pq[c0 * 16 + tok] = q;
    __syncthreads();
    if (threadIdx.x < 16) {
        float ss = 0.0f, qq = 0.0f;
        #pragma unroll
        for (int j = 0; j < 16; j++) { ss += ps[j * 16 + threadIdx.x]; qq += pq[j * 16 + threadIdx.x]; }
        float mean = ss * (1.0f / C_);
        float var  = qq * (1.0f / C_) - mean * mean;
        mrow[threadIdx.x] = mean;
        rrow[threadIdx.x] = rsqrtf(var + 1e-5f);
    }
    __syncthreads();
    const int tok2 = threadIdx.x >> 4, part = threadIdx.x & 15;
    const float mean = mrow[tok2], rstd = rrow[tok2];
    __half* yr = Y + (size_t)(b * N_ + n0 + tok2) * C_;
    #pragma unroll
    for (int i = 0; i < 24; i++) {
        int c = part + i * 16;
        float v = fs[c * 17 + tok2];
        yr[c] = __float2half((v - mean) * rstd * w[c] + bias[c]);
    }
}

// ---------------------------------------------------------------------------
// LayerNorm (rows of 384) from token-major fp32, fp16 output (LN2)
// ---------------------------------------------------------------------------
__global__ void ln16_k(const float* __restrict__ X, const float* __restrict__ w,
                       const float* __restrict__ bias, __half* __restrict__ Y) {
    int row = blockIdx.x;
    int tid = threadIdx.x;
    const float* xr = X + (size_t)row * C_;
    float v0 = xr[tid], v1 = xr[tid + 128], v2 = xr[tid + 256];
    float s = v0 + v1 + v2;
    float q = v0 * v0 + v1 * v1 + v2 * v2;
    #pragma unroll
    for (int o = 16; o > 0; o >>= 1) {
        s += __shfl_xor_sync(0xffffffffu, s, o);
        q += __shfl_xor_sync(0xffffffffu, q, o);
    }
    __shared__ float ss[4], sq[4];
    int wid = tid >> 5, lane = tid & 31;
    if (lane == 0) { ss[wid] = s; sq[wid] = q; }
    __syncthreads();
    s = ss[0] + ss[1] + ss[2] + ss[3];
    q = sq[0] + sq[1] + sq[2] + sq[3];
    float mean = s * (1.0f / C_);
    float var  = q * (1.0f / C_) - mean * mean;
    float rstd = rsqrtf(var + 1e-5f);
    __half* yr = Y + (size_t)row * C_;
    yr[tid]       = __float2half((v0 - mean) * rstd * w[tid]       + bias[tid]);
    yr[tid + 128] = __float2half((v1 - mean) * rstd * w[tid + 128] + bias[tid + 128]);
    yr[tid + 256] = __float2half((v2 - mean) * rstd * w[tid + 256] + bias[tid + 256]);
}

// ---------------------------------------------------------------------------
// fp16 mma.sync NT GEMM: BMx128 tile (BM = 128 or 256), 256 threads,
// warp tile (BM/4)x64, k-chunk 32, 3-stage cp.async pipeline, SW64 smem.
// ACT: 1 = exact GELU.
// RES: 0 none; 1 fp32 token-major (Res); 2 residual = x (B,C,N) transposed.
// OUT: 0 fp32 token-major; 1 fp16 token-major; 2 fp32 transposed (BM=128 only)
// ---------------------------------------------------------------------------
template<int BM, int ACT, int RES, int OUT>
__global__ __launch_bounds__(256)
void gemm16(const __half* __restrict__ A, const __half* __restrict__ Bw,
            const float* __restrict__ bias, const float* __restrict__ Res,
            const float* __restrict__ Xres,
            float* __restrict__ Cf, __half* __restrict__ Ch,
            int M, int N, int K) {
    constexpr int MI = BM / 64;                 // m16 tiles per warp / A-load iters
    constexpr int STAGE = (BM + 128) * 64;      // bytes per pipeline stage
    extern __shared__ __align__(128) char dsm[];
    const uint32_t base = smem_u32(dsm);
    const int tid = threadIdx.x, lane = tid & 31, warp = tid >> 5;
    const int wm = (warp & 3) * (BM / 4), wn = (warp >> 2) * 64;
    const int m0 = blockIdx.y * BM, n0 = blockIdx.x * 128;
    const int l8 = lane & 7, sub = lane >> 3;
    const int nc = K >> 5;

    float acc[MI][8][4];
    #pragma unroll
    for (int i = 0; i < MI; i++)
        #pragma unroll
        for (int j = 0; j < 8; j++)
            #pragma unroll
            for (int c = 0; c < 4; c++) acc[i][j][c] = 0.0f;

    #define ISSUE(st, k0)                                                        \
        do {                                                                     \
            _Pragma("unroll")                                                    \
            for (int t = 0; t < MI; t++) {                                       \
                int e = tid + t * 256;                                           \
                int r = e >> 2, cc = e & 3;                                      \
                cpasync16(base + (st) * STAGE + SW64((uint32_t)(r * 64 + cc * 16)), \
                          A + (size_t)(m0 + r) * K + (k0) + cc * 8);             \
            }                                                                    \
            _Pragma("unroll")                                                    \
            for (int t = 0; t < 2; t++) {                                        \
                int e = tid + t * 256;                                           \
                int r = e >> 2, cc = e & 3;                                      \
                cpasync16(base + (st) * STAGE + BM * 64 + SW64((uint32_t)(r * 64 + cc * 16)), \
                          Bw + (size_t)(n0 + r) * K + (k0) + cc * 8);            \
            }                                                                    \
            asm volatile("cp.async.commit_group;");                              \
        } while (0)

    ISSUE(0, 0);
    ISSUE(1, 32);

    for (int c = 0; c < nc; c++) {
        const int buf = c % 3;
        if (c + 1 < nc) { asm volatile("cp.async.wait_group 1;"); }
        else            { asm volatile("cp.async.wait_group 0;"); }
        __syncthreads();
        if (c + 2 < nc) ISSUE((c + 2) % 3, (c + 2) * 32);

        const uint32_t aA = base + buf * STAGE;
        const uint32_t aB = aA + BM * 64;
        #pragma unroll
        for (int kk = 0; kk < 2; kk++) {
            uint32_t af[MI][4];
            #pragma unroll
            for (int i = 0; i < MI; i++) {
                uint32_t off = (uint32_t)((wm + i * 16 + (sub & 1) * 8 + l8) * 64
                                          + kk * 32 + (sub >> 1) * 16);
                ldsm4(aA + SW64(off), af[i]);
            }
            #pragma unroll
            for (int jp = 0; jp < 4; jp++) {
                uint32_t bf[4];
                uint32_t off = (uint32_t)((wn + jp * 16 + (sub & 1) * 8 + l8) * 64
                                          + kk * 32 + (sub >> 1) * 16);
                ldsm4(aB + SW64(off), bf);
                #pragma unroll
                for (int i = 0; i < MI; i++) {
                    mmaf16(acc[i][2 * jp],     af[i], bf[0], bf[2]);
                    mmaf16(acc[i][2 * jp + 1], af[i], bf[1], bf[3]);
                }
            }
        }
        __syncthreads();
    }
    #undef ISSUE

    const int rq = lane >> 2, cq = (lane & 3) * 2;

    if (OUT == 2) {
        // staged transpose-out: out[b, col, n]  (BM = 128 instantiation only)
        float* stage = (float*)dsm;   // [128][65]
        const int bb = m0 >> 10;
        const int nbase = m0 & 1023;
        #pragma unroll 1
        for (int halfc = 0; halfc < 2; halfc++) {
            __syncthreads();
            if ((warp >> 2) == halfc) {
                #pragma unroll
                for (int i = 0; i < MI; i++)
                    #pragma unroll
                    for (int hrow = 0; hrow < 2; hrow++) {
                        int row_local = wm + i * 16 + rq + hrow * 8;
                        #pragma unroll
                        for (int j = 0; j < 8; j++) {
                            int col_local = j * 8 + cq;
                            int col = n0 + halfc * 64 + col_local;
                            float v0 = acc[i][j][hrow * 2 + 0] + bias[col];
                            float v1 = acc[i][j][hrow * 2 + 1] + bias[col + 1];
                            if (RES == 1) {
                                float2 r = *(const float2*)&Res[(size_t)(m0 + row_local) * N + col];
                                v0 += r.x; v1 += r.y;
                            }
                            stage[row_local * 65 + col_local]     = v0;
                            stage[row_local * 65 + col_local + 1] = v1;
                        }
                    }
            }
            __syncthreads();
            #pragma unroll
            for (int it = 0; it < 32; it++) {
                int idx = tid + it * 256;      // 0..8191
                int cl = idx >> 7, nl = idx & 127;
                Cf[((size_t)bb * C_ + n0 + halfc * 64 + cl) * N_ + nbase + nl]
                    = stage[nl * 65 + cl];
            }
        }
        return;
    }

    #pragma unroll
    for (int i = 0; i < MI; i++) {
        #pragma unroll
        for (int half = 0; half < 2; half++) {
            int row = m0 + wm + i * 16 + rq + half * 8;
            #pragma unroll
            for (int j = 0; j < 8; j++) {
                int col = n0 + wn + j * 8 + cq;
                size_t off = (size_t)row * N + col;
                float v0 = acc[i][j][half * 2 + 0] + bias[col];
                float v1 = acc[i][j][half * 2 + 1] + bias[col + 1];
                if (ACT == 1) {
                    v0 = 0.5f * v0 * (1.0f + erff(v0 * 0.70710678118654752f));
                    v1 = 0.5f * v1 * (1.0f + erff(v1 * 0.70710678118654752f));
                }
                if (RES == 1) {
                    float2 r = *(const float2*)&Res[off];
                    v0 += r.x; v1 += r.y;
                }
                if (RES == 2) {
                    int bb = row >> 10, nn = row & 1023;
                    v0 += Xres[((size_t)bb * C_ + col)     * N_ + nn];
                    v1 += Xres[((size_t)bb * C_ + col + 1) * N_ + nn];
                }
                if (OUT == 1) {
                    *(__half2*)&Ch[off] = __floats2half2_rn(v0, v1);
                } else {
                    *(float2*)&Cf[off] = make_float2(v0, v1);
                }
            }
        }
    }
}

// ---------------------------------------------------------------------------
// Tensor-core flash attention, cp.async double-buffered K/V.
// exp via ex2.approx.f16x2; row-sum l via ones-column MMA; Q pre-scaled.
// CTA = (b, h, 128-query tile), 128 threads, 2 CTAs/SM.
// dsm layout: Q@0 (16KB) | K0@16K | V0@32K | K1@48K | V1@64K   (80KB)
// ---------------------------------------------------------------------------
#define ATTN_DSM 81920
__global__ __launch_bounds__(128, 2)
void attn_mma(const __half* __restrict__ qkv16, __half* __restrict__ att16) {
    extern __shared__ __align__(128) char dsm[];
    const uint32_t base = smem_u32(dsm);
    const int tid = threadIdx.x, lane = tid & 31, warp = tid >> 5;
    const int bh = blockIdx.y, b = bh >> 3, h = bh & 7;
    const int tok0 = b * N_ + blockIdx.x * 128;
    const float kscale = 0.14433756729740643f * 1.4426950408889634f;  // scale*log2e
    const int l8 = lane & 7, sub = lane >> 3;
    const int wm = warp * 32;

    // Q tile (regular stores)
    {
        const uint4* src = (const uint4*)(qkv16 + (size_t)(tok0 + tid) * QKVC + h * HD);
        #pragma unroll
        for (int j = 0; j < 6; j++)
            *(uint4*)(dsm + SW128((uint32_t)(tid * 128 + j * 16))) = src[j];
    }
    // ones column (col 48 = 1.0, 49..63 = 0) in both V buffers — cp.async only
    // touches byte range [0,96) per row, so these persist.
    #pragma unroll
    for (int bufi = 0; bufi < 2; bufi++) {
        char* vb = dsm + 32768 + bufi * 32768;
        *(uint4*)(vb + SW128((uint32_t)(tid * 128 + 96)))  = make_uint4(0x3C00u, 0, 0, 0);
        *(uint4*)(vb + SW128((uint32_t)(tid * 128 + 112))) = make_uint4(0, 0, 0, 0);
    }

    #define ISSUE_KV(bufi, kt)                                                   \
        do {                                                                     \
            int tk = b * N_ + (kt) * 128 + tid;                                  \
            const __half* kp = qkv16 + (size_t)tk * QKVC + C_     + h * HD;      \
            const __half* vp = qkv16 + (size_t)tk * QKVC + 2 * C_ + h * HD;      \
            uint32_t kb = base + 16384 + (bufi) * 32768;                         \
            _Pragma("unroll")                                                    \
            for (int j = 0; j < 6; j++) {                                        \
                uint32_t so = SW128((uint32_t)(tid * 128 + j * 16));             \
                cpasync16(kb + so,         kp + j * 8);                          \
                cpasync16(kb + 16384 + so, vp + j * 8);                          \
            }                                                                    \
            asm volatile("cp.async.commit_group;");                              \
        } while (0)

    ISSUE_KV(0, 0);
    __syncthreads();   // Q + ones visible

    // Q fragments, pre-scaled by kscale (fp16)
    const uint32_t ksc2 = packh2(kscale, kscale);
    uint32_t qa[2][3][4];
    #pragma unroll
    for (int i = 0; i < 2; i++)
        #pragma unroll
        for (int ks = 0; ks < 3; ks++) {
            uint32_t off = (uint32_t)((wm + i * 16 + (sub & 1) * 8 + l8) * 128
                                      + ks * 32 + (sub >> 1) * 16);
            ldsm4(base + SW128(off), qa[i][ks]);
            #pragma unroll
            for (int q = 0; q < 4; q++) qa[i][ks][q] = h2mul(qa[i][ks][q], ksc2);
        }

    float o[2][7][4];
    #pragma unroll
    for (int i = 0; i < 2; i++)
        #pragma unroll
        for (int j = 0; j < 7; j++)
            #pragma unroll
            for (int c = 0; c < 4; c++) o[i][j][c] = 0.0f;

    for (int kt = 0; kt < 8; kt++) {
        const int buf = kt & 1;
        if (kt + 1 < 8) {
            ISSUE_KV(buf ^ 1, kt + 1);
            asm volatile("cp.async.wait_group 1;");
        } else {
            asm volatile("cp.async.wait_group 0;");
        }
        __syncthreads();

        const uint32_t aK = base + 16384 + buf * 32768;
        const uint32_t aV = aK + 16384;

        #pragma unroll
        for (int kh = 0; kh < 2; kh++) {
            float s[2][8][4];
            #pragma unroll
            for (int i = 0; i < 2; i++)
                #pragma unroll
                for (int j = 0; j < 8; j++)
                    #pragma unroll
                    for (int c = 0; c < 4; c++) s[i][j][c] = 0.0f;

            #pragma unroll
            for (int ks = 0; ks < 3; ks++) {
                #pragma unroll
                for (int jp = 0; jp < 4; jp++) {
                    uint32_t bf[4];
                    uint32_t off = (uint32_t)((kh * 64 + jp * 16 + (sub & 1) * 8 + l8) * 128
                                              + ks * 32 + (sub >> 1) * 16);
                    ldsm4(aK + SW128(off), bf);
                    #pragma unroll
                    for (int i = 0; i < 2; i++) {
                        mmaf16(s[i][2 * jp],     qa[i][ks], bf[0], bf[2]);
                        mmaf16(s[i][2 * jp + 1], qa[i][ks], bf[1], bf[3]);
                    }
                }
            }

            // P = 2^s (Q pre-scaled) packed fp16
            uint32_t ph[2][8][2];
            #pragma unroll
            for (int i = 0; i < 2; i++)
                #pragma unroll
                for (int j = 0; j < 8; j++) {
                    ph[i][j][0] = h2ex2(packh2(s[i][j][0], s[i][j][1]));
                    ph[i][j][1] = h2ex2(packh2(s[i][j][2], s[i][j][3]));
                }

            // O += P V ; l accumulates in col 48 (ones column)
            #pragma unroll
            for (int t = 0; t < 4; t++) {
                uint32_t vb[4][4];
                #pragma unroll
                for (int jdp = 0; jdp < 4; jdp++) {
                    uint32_t off = (uint32_t)((kh * 64 + t * 16 + (sub & 1) * 8 + l8) * 128
                                              + jdp * 32 + (sub >> 1) * 16);
                    ldsm4t(aV + SW128(off), vb[jdp]);
                }
                #pragma unroll
                for (int i = 0; i < 2; i++) {
                    uint32_t a0 = ph[i][2 * t][0],     a1 = ph[i][2 * t][1];
                    uint32_t a2 = ph[i][2 * t + 1][0], a3 = ph[i][2 * t + 1][1];
                    #pragma unroll
                    for (int jdp = 0; jdp < 3; jdp++) {
                        mmaf16v(o[i][2 * jdp],     a0, a1, a2, a3, vb[jdp][0], vb[jdp][1]);
                        mmaf16v(o[i][2 * jdp + 1], a0, a1, a2, a3, vb[jdp][2], vb[jdp][3]);
                    }
                    mmaf16v(o[i][6], a0, a1, a2, a3, vb[3][0], vb[3][1]);
                }
            }
        }
        __syncthreads();   // all reads of buf done before next ISSUE overwrites it
    }
    #undef ISSUE_KV

    const int rq = lane >> 2, cq = (lane & 3) * 2;
    #pragma unroll
    for (int i = 0; i < 2; i++) {
        float l0 = __shfl_sync(0xffffffffu, o[i][6][0], lane & 0x1c);
        float l1 = __shfl_sync(0xffffffffu, o[i][6][2], lane & 0x1c);
        float inv0 = 1.0f / l0, inv1 = 1.0f / l1;
        int r0 = tok0 + wm + i * 16 + rq;
        #pragma unroll
        for (int j = 0; j < 6; j++) {
            int col = h * HD + j * 8 + cq;
            *(__half2*)&att16[(size_t)r0 * C_ + col] =
                __floats2half2_rn(o[i][j][0] * inv0, o[i][j][1] * inv0);
            *(__half2*)&att16[(size_t)(r0 + 8) * C_ + col] =
                __floats2half2_rn(o[i][j][2] * inv1, o[i][j][3] * inv1);
        }
    }
}

// ---------------------------------------------------------------------------
// Launch
// ---------------------------------------------------------------------------
#define DSM_128 49152
#define DSM_256 73728

extern "C" void kernel_launch(void* const* d_in, const int* in_sizes, int n_in,
                              void* d_out, int out_size) {
    const float* x     = (const float*)d_in[0];
    const float* ln1w  = (const float*)d_in[1];
    const float* ln1b  = (const float*)d_in[2];
    const float* qkvw  = (const float*)d_in[3];
    const float* qkvb  = (const float*)d_in[4];
    const float* projw = (const float*)d_in[5];
    const float* projb = (const float*)d_in[6];
    const float* ln2w  = (const float*)d_in[7];
    const float* ln2b  = (const float*)d_in[8];
    const float* fc1w  = (const float*)d_in[9];
    const float* fc1b  = (const float*)d_in[10];
    const float* fc2w  = (const float*)d_in[11];
    const float* fc2b  = (const float*)d_in[12];

    float *x2;
    __half *h16, *qkv16, *att16, *mid16, *w16;
    cudaGetSymbolAddress((void**)&x2,    g_x2);
    cudaGetSymbolAddress((void**)&h16,   g_h16);
    cudaGetSymbolAddress((void**)&qkv16, g_qkv16);
    cudaGetSymbolAddress((void**)&att16, g_att16);
    cudaGetSymbolAddress((void**)&mid16, g_mid16);
    cudaGetSymbolAddress((void**)&w16,   g_w16);

    cudaFuncSetAttribute(gemm16<256,0,0,1>, cudaFuncAttributeMaxDynamicSharedMemorySize, DSM_256);
    cudaFuncSetAttribute(gemm16<256,0,2,0>, cudaFuncAttributeMaxDynamicSharedMemorySize, DSM_256);
    cudaFuncSetAttribute(gemm16<256,1,0,1>, cudaFuncAttributeMaxDynamicSharedMemorySize, DSM_256);
    cudaFuncSetAttribute(gemm16<128,0,1,2>, cudaFuncAttributeMaxDynamicSharedMemorySize, DSM_128);
    cudaFuncSetAttribute(attn_mma, cudaFuncAttributeMaxDynamicSharedMemorySize, ATTN_DSM);

    // 1. weights fp32 -> fp16
    cvt_all<<<1728, 256>>>(qkvw, projw, fc1w, fc2w, w16);
    // 2. fused transpose + LN1: x -> h16
    transln_k<<<dim3(N_/16, B_), 256>>>(x, ln1w, ln1b, h16);
    // 3. QKV projection (fp16 out)
    gemm16<256,0,0,1><<<dim3(QKVC/128, M_/256), 256, DSM_256>>>(
        h16, w16 + W_QKV, qkvb, nullptr, nullptr, nullptr, qkv16, M_, QKVC, C_);
    // 4. attention (fp16 out)
    attn_mma<<<dim3(N_/128, B_*NH), 128, ATTN_DSM>>>(qkv16, att16);
    // 5. proj + residual(x, transposed on the fly) -> x2 fp32
    gemm16<256,0,2,0><<<dim3(C_/128, M_/256), 256, DSM_256>>>(
        att16, w16 + W_PROJ, projb, nullptr, x, x2, nullptr, M_, C_, C_);
    // 6. LN2 -> fp16
    ln16_k<<<M_, 128>>>(x2, ln2w, ln2b, h16);
    // 7. fc1 + GELU (fp16 out)
    gemm16<256,1,0,1><<<dim3(HID/128, M_/256), 256, DSM_256>>>(
        h16, w16 + W_FC1, fc1b, nullptr, nullptr, nullptr, mid16, M_, HID, C_);
    // 8. fc2 + residual(x2), transposed epilogue -> d_out (B,C,N)
    gemm16<128,0,1,2><<<dim3(C_/128, M_/128), 256, DSM_128>>>(
        mid16, w16 + W_FC2, fc2b, x2, nullptr, (float*)d_out, nullptr, M_, C_, HID);
}

// round 14
// speedup vs baseline: 1.0350x; 1.0350x over previous
#include <cuda_runtime.h>
#include <cuda_fp16.h>
#include <math.h>
#include <stdint.h>

// Problem constants
#define B_   16
#define C_   384
#define N_   1024
#define NH   8
#define HD   48
#define HID  1536
#define M_   (B_*N_)     // 16384 tokens
#define QKVC (3*C_)      // 1152

// ---------------------------------------------------------------------------
// Scratch
// ---------------------------------------------------------------------------
__device__ float  g_x2 [M_*C_];
__device__ __half g_h16 [M_*C_];
__device__ __half g_qkv16[M_*QKVC];
__device__ __half g_att16[M_*C_];
__device__ __half g_mid16[M_*HID];
__device__ __half g_w16[1769472];
#define W_QKV 0
#define W_PROJ 442368
#define W_FC1 589824
#define W_FC2 1179648

// ---------------------------------------------------------------------------
// Helpers
// ---------------------------------------------------------------------------
__device__ __forceinline__ uint32_t smem_u32(const void* p) {
    uint32_t a;
    asm("{ .reg .u64 t; cvta.to.shared.u64 t, %1; cvt.u32.u64 %0, t; }"
        : "=r"(a) : "l"(p));
    return a;
}
#define SW64(o)  ((o) ^ (((o) >> 3) & 0x30))
#define SW128(o) ((o) ^ (((o) >> 3) & 0x70))

__device__ __forceinline__ void ldsm4(uint32_t addr, uint32_t r[4]) {
    asm volatile("ldmatrix.sync.aligned.m8n8.x4.shared.b16 {%0,%1,%2,%3}, [%4];"
                 : "=r"(r[0]), "=r"(r[1]), "=r"(r[2]), "=r"(r[3]) : "r"(addr));
}
__device__ __forceinline__ void ldsm4t(uint32_t addr, uint32_t r[4]) {
    asm volatile("ldmatrix.sync.aligned.m8n8.x4.trans.shared.b16 {%0,%1,%2,%3}, [%4];"
                 : "=r"(r[0]), "=r"(r[1]), "=r"(r[2]), "=r"(r[3]) : "r"(addr));
}
__device__ __forceinline__ void mmaf16(float* c, const uint32_t* a,
                                       uint32_t b0, uint32_t b1) {
    asm volatile("mma.sync.aligned.m16n8k16.row.col.f32.f16.f16.f32 "
                 "{%0,%1,%2,%3}, {%4,%5,%6,%7}, {%8,%9}, {%0,%1,%2,%3};"
                 : "+f"(c[0]), "+f"(c[1]), "+f"(c[2]), "+f"(c[3])
                 : "r"(a[0]), "r"(a[1]), "r"(a[2]), "r"(a[3]), "r"(b0), "r"(b1));
}
__device__ __forceinline__ void mmaf16v(float* c, uint32_t a0, uint32_t a1,
                                        uint32_t a2, uint32_t a3,
                                        uint32_t b0, uint32_t b1) {
    asm volatile("mma.sync.aligned.m16n8k16.row.col.f32.f16.f16.f32 "
                 "{%0,%1,%2,%3}, {%4,%5,%6,%7}, {%8,%9}, {%0,%1,%2,%3};"
                 : "+f"(c[0]), "+f"(c[1]), "+f"(c[2]), "+f"(c[3])
                 : "r"(a0), "r"(a1), "r"(a2), "r"(a3), "r"(b0), "r"(b1));
}
__device__ __forceinline__ void cpasync16(uint32_t s, const void* g) {
    asm volatile("cp.async.cg.shared.global [%0], [%1], 16;" :: "r"(s), "l"(g));
}
__device__ __forceinline__ uint32_t packh2(float x, float y) {
    __half2 t = __floats2half2_rn(x, y);
    return *(uint32_t*)&t;
}
__device__ __forceinline__ uint32_t h2ex2(uint32_t x) {
    uint32_t r;
    asm("ex2.approx.f16x2 %0, %1;" : "=r"(r) : "r"(x));
    return r;
}
__device__ __forceinline__ uint32_t h2mul(uint32_t a, uint32_t b) {
    uint32_t r;
    asm("mul.f16x2 %0, %1, %2;" : "=r"(r) : "r"(a), "r"(b));
    return r;
}

// ---------------------------------------------------------------------------
// All weights fp32 -> fp16 in one launch
// ---------------------------------------------------------------------------
__global__ void cvt_all(const float* __restrict__ qkvw, const float* __restrict__ projw,
                        const float* __restrict__ fc1w, const float* __restrict__ fc2w,
                        __half* __restrict__ w16) {
    int i = blockIdx.x * 256 + threadIdx.x;   // 0 .. 442367
    const float* s;
    __half* d;
    if (i < 110592)      { s = qkvw;  d = w16 + W_QKV;  }
    else if (i < 147456) { s = projw; d = w16 + W_PROJ; i -= 110592; }
    else if (i < 294912) { s = fc1w;  d = w16 + W_FC1;  i -= 147456; }
    else                 { s = fc2w;  d = w16 + W_FC2;  i -= 294912; }
    float4 v = ((const float4*)s)[i];
    __half2* dp = (__half2*)d;
    dp[2 * i]     = __floats2half2_rn(v.x, v.y);
    dp[2 * i + 1] = __floats2half2_rn(v.z, v.w);
}

// ---------------------------------------------------------------------------
// Fused transpose + LayerNorm: x (B,C,N) fp32 -> h16 (B,N,C) fp16
// ---------------------------------------------------------------------------
__global__ __launch_bounds__(256)
void transln_k(const float* __restrict__ x, const float* __restrict__ w,
               const float* __restrict__ bias, __half* __restrict__ Y) {
    __shared__ float fs[384 * 17];
    __shared__ float ps[256], pq[256];
    __shared__ float mrow[16], rrow[16];
    const int b = blockIdx.y, n0 = blockIdx.x * 16;
    const int tok = threadIdx.x & 15, c0 = threadIdx.x >> 4;
    const float* xb = x + (size_t)b * C_ * N_ + n0;
    float s = 0.0f, q = 0.0f;
    #pragma unroll
    for (int i = 0; i < 24; i++) {
        int c = c0 + i * 16;
        float v = xb[(size_t)c * N_ + tok];
        s += v; q += v * v;
        fs[c * 17 + tok] = v;
    }
    ps[c0 * 16 + tok] = s;
    pq[c0 * 16 + tok] = q;
    __syncthreads();
    if (threadIdx.x < 16) {
        float ss = 0.0f, qq = 0.0f;
        #pragma unroll
        for (int j = 0; j < 16; j++) { ss += ps[j * 16 + threadIdx.x]; qq += pq[j * 16 + threadIdx.x]; }
        float mean = ss * (1.0f / C_);
        float var  = qq * (1.0f / C_) - mean * mean;
        mrow[threadIdx.x] = mean;
        rrow[threadIdx.x] = rsqrtf(var + 1e-5f);
    }
    __syncthreads();
    const int tok2 = threadIdx.x >> 4, part = threadIdx.x & 15;
    const float mean = mrow[tok2], rstd = rrow[tok2];
    __half* yr = Y + (size_t)(b * N_ + n0 + tok2) * C_;
    #pragma unroll
    for (int i = 0; i < 24; i++) {
        int c = part + i * 16;
        float v = fs[c * 17 + tok2];
        yr[c] = __float2half((v - mean) * rstd * w[c] + bias[c]);
    }
}

// ---------------------------------------------------------------------------
// LayerNorm (rows of 384) from token-major fp32, fp16 output (LN2)
// ---------------------------------------------------------------------------
__global__ void ln16_k(const float* __restrict__ X, const float* __restrict__ w,
                       const float* __restrict__ bias, __half* __restrict__ Y) {
    int row = blockIdx.x;
    int tid = threadIdx.x;
    const float* xr = X + (size_t)row * C_;
    float v0 = xr[tid], v1 = xr[tid + 128], v2 = xr[tid + 256];
    float s = v0 + v1 + v2;
    float q = v0 * v0 + v1 * v1 + v2 * v2;
    #pragma unroll
    for (int o = 16; o > 0; o >>= 1) {
        s += __shfl_xor_sync(0xffffffffu, s, o);
        q += __shfl_xor_sync(0xffffffffu, q, o);
    }
    __shared__ float ss[4], sq[4];
    int wid = tid >> 5, lane = tid & 31;
    if (lane == 0) { ss[wid] = s; sq[wid] = q; }
    __syncthreads();
    s = ss[0] + ss[1] + ss[2] + ss[3];
    q = sq[0] + sq[1] + sq[2] + sq[3];
    float mean = s * (1.0f / C_);
    float var  = q * (1.0f / C_) - mean * mean;
    float rstd = rsqrtf(var + 1e-5f);
    __half* yr = Y + (size_t)row * C_;
    yr[tid]       = __float2half((v0 - mean) * rstd * w[tid]       + bias[tid]);
    yr[tid + 128] = __float2half((v1 - mean) * rstd * w[tid + 128] + bias[tid + 128]);
    yr[tid + 256] = __float2half((v2 - mean) * rstd * w[tid + 256] + bias[tid + 256]);
}

// ---------------------------------------------------------------------------
// fp16 mma.sync NT GEMM: 128x128 tile, 256 threads (8 warps 4Mx2N, warp 32x64),
// k-chunk 32, 4-stage cp.async pipeline, SW64 smem, ldmatrix.x4.
// ACT: 1 = exact GELU.
// RES: 0 none; 1 fp32 token-major (Res).
// OUT: 0 fp32 token-major; 1 fp16 token-major;
//      2 fp32 transposed to (B,C,N) via smem staging (fc2 -> d_out);
//      3 fp32 token-major with residual = x (B,C,N) added via coalesced
//        smem-staged transpose (proj -> x2).
// Dynamic smem: 4 stages x 16KB = 64KB
// ---------------------------------------------------------------------------
template<int ACT, int RES, int OUT>
__global__ __launch_bounds__(256)
void gemm16(const __half* __restrict__ A, const __half* __restrict__ Bw,
            const float* __restrict__ bias, const float* __restrict__ Res,
            const float* __restrict__ Xres,
            float* __restrict__ Cf, __half* __restrict__ Ch,
            int M, int N, int K) {
    extern __shared__ __align__(128) char dsm[];
    const uint32_t base = smem_u32(dsm);
    const int tid = threadIdx.x, lane = tid & 31, warp = tid >> 5;
    const int wm = (warp & 3) * 32, wn = (warp >> 2) * 64;
    const int m0 = blockIdx.y * 128, n0 = blockIdx.x * 128;
    const int l8 = lane & 7, sub = lane >> 3;
    const int nc = K >> 5;

    float acc[2][8][4];
    #pragma unroll
    for (int i = 0; i < 2; i++)
        #pragma unroll
        for (int j = 0; j < 8; j++)
            #pragma unroll
            for (int c = 0; c < 4; c++) acc[i][j][c] = 0.0f;

    #define ISSUE(st, k0)                                                        \
        do {                                                                     \
            _Pragma("unroll")                                                    \
            for (int t = 0; t < 2; t++) {                                        \
                int e = tid + t * 256;                                           \
                int r = e >> 2, cc = e & 3;                                      \
                uint32_t so = SW64((uint32_t)(r * 64 + cc * 16));                \
                cpasync16(base + (st) * 16384 + so,                              \
                          A + (size_t)(m0 + r) * K + (k0) + cc * 8);             \
                cpasync16(base + (st) * 16384 + 8192 + so,                       \
                          Bw + (size_t)(n0 + r) * K + (k0) + cc * 8);            \
            }                                                                    \
            asm volatile("cp.async.commit_group;");                              \
        } while (0)

    ISSUE(0, 0);
    ISSUE(1, 32);
    ISSUE(2, 64);

    for (int c = 0; c < nc; c++) {
        const int buf = c & 3;
        const int rem = nc - 1 - c;
        if (rem >= 2)      { asm volatile("cp.async.wait_group 2;"); }
        else if (rem == 1) { asm volatile("cp.async.wait_group 1;"); }
        else               { asm volatile("cp.async.wait_group 0;"); }
        __syncthreads();
        if (c + 3 < nc) ISSUE((c + 3) & 3, (c + 3) * 32);

        const uint32_t aA = base + buf * 16384;
        const uint32_t aB = aA + 8192;
        #pragma unroll
        for (int kk = 0; kk < 2; kk++) {
            uint32_t af[2][4];
            #pragma unroll
            for (int i = 0; i < 2; i++) {
                uint32_t off = (uint32_t)((wm + i * 16 + (sub & 1) * 8 + l8) * 64
                                          + kk * 32 + (sub >> 1) * 16);
                ldsm4(aA + SW64(off), af[i]);
            }
            #pragma unroll
            for (int jp = 0; jp < 4; jp++) {
                uint32_t bf[4];
                uint32_t off = (uint32_t)((wn + jp * 16 + (sub & 1) * 8 + l8) * 64
                                          + kk * 32 + (sub >> 1) * 16);
                ldsm4(aB + SW64(off), bf);
                #pragma unroll
                for (int i = 0; i < 2; i++) {
                    mmaf16(acc[i][2 * jp],     af[i], bf[0], bf[2]);
                    mmaf16(acc[i][2 * jp + 1], af[i], bf[1], bf[3]);
                }
            }
        }
        // no trailing __syncthreads — the leading sync of iteration c+1
        // orders the last reads of buffer (c+3)&3 before ISSUE overwrites it.
    }
    #undef ISSUE

    const int rq = lane >> 2, cq = (lane & 3) * 2;

    if (OUT == 3) {
        // proj path: v = acc + bias; v += x[b, col, n] (coalesced);
        // write x2 token-major (coalesced). Rotation-swizzled smem stage.
        float* stage = (float*)dsm;                 // 128x128 fp32 = 64KB
        const int bb = m0 >> 10, nbase = m0 & 1023;
        __syncthreads();                            // all warps out of mainloop
        #pragma unroll
        for (int i = 0; i < 2; i++)
            #pragma unroll
            for (int half = 0; half < 2; half++) {
                int row = wm + i * 16 + rq + half * 8;     // token local
                #pragma unroll
                for (int j = 0; j < 8; j++) {
                    int col = wn + j * 8 + cq;             // col local
                    stage[row * 128 + ((col     + row) & 127)]
                        = acc[i][j][half * 2 + 0] + bias[n0 + col];
                    stage[row * 128 + ((col + 1 + row) & 127)]
                        = acc[i][j][half * 2 + 1] + bias[n0 + col + 1];
                }
            }
        __syncthreads();
        // add x: lanes sweep token dim (coalesced gmem read). Full 128x128 tile.
        #pragma unroll
        for (int it = 0; it < 64; it++) {
            int idx = tid + it * 256;                // 0..16383
            int cl = idx >> 7, tl = idx & 127;
            stage[tl * 128 + ((cl + tl) & 127)]
                += Xres[((size_t)bb * C_ + n0 + cl) * N_ + nbase + tl];
        }
        __syncthreads();
        // write x2 token-major: lanes sweep col dim (coalesced gmem write)
        #pragma unroll
        for (int it = 0; it < 64; it++) {
            int idx = tid + it * 256;                // 0..16383
            int tl = idx >> 7, cl = idx & 127;
            Cf[(size_t)(m0 + tl) * C_ + n0 + cl] = stage[tl * 128 + ((cl + tl) & 127)];
        }
        return;
    }

    if (OUT == 2) {
        // staged transpose-out: out[b, col, n]
        float* stage = (float*)dsm;   // [128][65]
        const int bb = m0 >> 10;
        const int nbase = m0 & 1023;
        #pragma unroll 1
        for (int halfc = 0; halfc < 2; halfc++) {
            __syncthreads();
            if ((warp >> 2) == halfc) {
                #pragma unroll
                for (int i = 0; i < 2; i++)
                    #pragma unroll
                    for (int hrow = 0; hrow < 2; hrow++) {
                        int row_local = wm + i * 16 + rq + hrow * 8;
                        #pragma unroll
                        for (int j = 0; j < 8; j++) {
                            int col_local = j * 8 + cq;
                            int col = n0 + halfc * 64 + col_local;
                            float v0 = acc[i][j][hrow * 2 + 0] + bias[col];
                            float v1 = acc[i][j][hrow * 2 + 1] + bias[col + 1];
                            if (RES == 1) {
                                float2 r = *(const float2*)&Res[(size_t)(m0 + row_local) * N + col];
                                v0 += r.x; v1 += r.y;
                            }
                            stage[row_local * 65 + col_local]     = v0;
                            stage[row_local * 65 + col_local + 1] = v1;
                        }
                    }
            }
            __syncthreads();
            #pragma unroll
            for (int it = 0; it < 32; it++) {
                int idx = tid + it * 256;      // 0..8191 (64 cols x 128 tokens)
                int cl = idx >> 7, nl = idx & 127;
                Cf[((size_t)bb * C_ + n0 + halfc * 64 + cl) * N_ + nbase + nl]
                    = stage[nl * 65 + cl];
            }
        }
        return;
    }

    #pragma unroll
    for (int i = 0; i < 2; i++) {
        #pragma unroll
        for (int half = 0; half < 2; half++) {
            int row = m0 + wm + i * 16 + rq + half * 8;
            #pragma unroll
            for (int j = 0; j < 8; j++) {
                int col = n0 + wn + j * 8 + cq;
                size_t off = (size_t)row * N + col;
                float v0 = acc[i][j][half * 2 + 0] + bias[col];
                float v1 = acc[i][j][half * 2 + 1] + bias[col + 1];
                if (ACT == 1) {
                    v0 = 0.5f * v0 * (1.0f + erff(v0 * 0.70710678118654752f));
                    v1 = 0.5f * v1 * (1.0f + erff(v1 * 0.70710678118654752f));
                }
                if (RES == 1) {
                    float2 r = *(const float2*)&Res[off];
                    v0 += r.x; v1 += r.y;
                }
                if (OUT == 1) {
                    *(__half2*)&Ch[off] = __floats2half2_rn(v0, v1);
                } else {
                    *(float2*)&Cf[off] = make_float2(v0, v1);
                }
            }
        }
    }
}

// ---------------------------------------------------------------------------
// Tensor-core flash attention, cp.async double-buffered K/V.
// exp via ex2.approx.f16x2; row-sum l via ones-column MMA; Q pre-scaled.
// CTA = (b, h, 128-query tile), 128 threads, 2 CTAs/SM.
// dsm layout: Q@0 (16KB) | K0@16K | V0@32K | K1@48K | V1@64K   (80KB)
// ---------------------------------------------------------------------------
#define ATTN_DSM 81920
__global__ __launch_bounds__(128, 2)
void attn_mma(const __half* __restrict__ qkv16, __half* __restrict__ att16) {
    extern __shared__ __align__(128) char dsm[];
    const uint32_t base = smem_u32(dsm);
    const int tid = threadIdx.x, lane = tid & 31, warp = tid >> 5;
    const int bh = blockIdx.y, b = bh >> 3, h = bh & 7;
    const int tok0 = b * N_ + blockIdx.x * 128;
    const float kscale = 0.14433756729740643f * 1.4426950408889634f;  // scale*log2e
    const int l8 = lane & 7, sub = lane >> 3;
    const int wm = warp * 32;

    // Q tile
    {
        const uint4* src = (const uint4*)(qkv16 + (size_t)(tok0 + tid) * QKVC + h * HD);
        #pragma unroll
        for (int j = 0; j < 6; j++)
            *(uint4*)(dsm + SW128((uint32_t)(tid * 128 + j * 16))) = src[j];
    }
    // ones column (col 48 = 1.0, 49..63 = 0) in both V buffers — cp.async only
    // touches byte range [0,96) per row, so these persist.
    #pragma unroll
    for (int bufi = 0; bufi < 2; bufi++) {
        char* vb = dsm + 32768 + bufi * 32768;
        *(uint4*)(vb + SW128((uint32_t)(tid * 128 + 96)))  = make_uint4(0x3C00u, 0, 0, 0);
        *(uint4*)(vb + SW128((uint32_t)(tid * 128 + 112))) = make_uint4(0, 0, 0, 0);
    }

    #define ISSUE_KV(bufi, kt)                                                   \
        do {                                                                     \
            int tk = b * N_ + (kt) * 128 + tid;                                  \
            const __half* kp = qkv16 + (size_t)tk * QKVC + C_     + h * HD;      \
            const __half* vp = qkv16 + (size_t)tk * QKVC + 2 * C_ + h * HD;      \
            uint32_t kb = base + 16384 + (bufi) * 32768;                         \
            _Pragma("unroll")                                                    \
            for (int j = 0; j < 6; j++) {                                        \
                uint32_t so = SW128((uint32_t)(tid * 128 + j * 16));             \
                cpasync16(kb + so,         kp + j * 8);                          \
                cpasync16(kb + 16384 + so, vp + j * 8);                          \
            }                                                                    \
            asm volatile("cp.async.commit_group;");                              \
        } while (0)

    ISSUE_KV(0, 0);
    __syncthreads();   // Q + ones visible

    // Q fragments, pre-scaled by kscale
    const uint32_t ksc2 = packh2(kscale, kscale);
    uint32_t qa[2][3][4];
    #pragma unroll
    for (int i = 0; i < 2; i++)
        #pragma unroll
        for (int ks = 0; ks < 3; ks++) {
            uint32_t off = (uint32_t)((wm + i * 16 + (sub & 1) * 8 + l8) * 128
                                      + ks * 32 + (sub >> 1) * 16);
            ldsm4(base + SW128(off), qa[i][ks]);
            #pragma unroll
            for (int q = 0; q < 4; q++) qa[i][ks][q] = h2mul(qa[i][ks][q], ksc2);
        }

    float o[2][7][4];
    #pragma unroll
    for (int i = 0; i < 2; i++)
        #pragma unroll
        for (int j = 0; j < 7; j++)
            #pragma unroll
            for (int c = 0; c < 4; c++) o[i][j][c] = 0.0f;

    for (int kt = 0; kt < 8; kt++) {
        const int buf = kt & 1;
        if (kt + 1 < 8) {
            ISSUE_KV(buf ^ 1, kt + 1);
            asm volatile("cp.async.wait_group 1;");
        } else {
            asm volatile("cp.async.wait_group 0;");
        }
        __syncthreads();

        const uint32_t aK = base + 16384 + buf * 32768;
        const uint32_t aV = aK + 16384;

        #pragma unroll
        for (int kh = 0; kh < 2; kh++) {
            float s[2][8][4];
            #pragma unroll
            for (int i = 0; i < 2; i++)
                #pragma unroll
                for (int j = 0; j < 8; j++)
                    #pragma unroll
                    for (int c = 0; c < 4; c++) s[i][j][c] = 0.0f;

            #pragma unroll
            for (int ks = 0; ks < 3; ks++) {
                #pragma unroll
                for (int jp = 0; jp < 4; jp++) {
                    uint32_t bf[4];
                    uint32_t off = (uint32_t)((kh * 64 + jp * 16 + (sub & 1) * 8 + l8) * 128
                                              + ks * 32 + (sub >> 1) * 16);
                    ldsm4(aK + SW128(off), bf);
                    #pragma unroll
                    for (int i = 0; i < 2; i++) {
                        mmaf16(s[i][2 * jp],     qa[i][ks], bf[0], bf[2]);
                        mmaf16(s[i][2 * jp + 1], qa[i][ks], bf[1], bf[3]);
                    }
                }
            }

            uint32_t ph[2][8][2];
            #pragma unroll
            for (int i = 0; i < 2; i++)
                #pragma unroll
                for (int j = 0; j < 8; j++) {
                    ph[i][j][0] = h2ex2(packh2(s[i][j][0], s[i][j][1]));
                    ph[i][j][1] = h2ex2(packh2(s[i][j][2], s[i][j][3]));
                }

            #pragma unroll
            for (int t = 0; t < 4; t++) {
                uint32_t vb[4][4];
                #pragma unroll
                for (int jdp = 0; jdp < 4; jdp++) {
                    uint32_t off = (uint32_t)((kh * 64 + t * 16 + (sub & 1) * 8 + l8) * 128
                                              + jdp * 32 + (sub >> 1) * 16);
                    ldsm4t(aV + SW128(off), vb[jdp]);
                }
                #pragma unroll
                for (int i = 0; i < 2; i++) {
                    uint32_t a0 = ph[i][2 * t][0],     a1 = ph[i][2 * t][1];
                    uint32_t a2 = ph[i][2 * t + 1][0], a3 = ph[i][2 * t + 1][1];
                    #pragma unroll
                    for (int jdp = 0; jdp < 3; jdp++) {
                        mmaf16v(o[i][2 * jdp],     a0, a1, a2, a3, vb[jdp][0], vb[jdp][1]);
                        mmaf16v(o[i][2 * jdp + 1], a0, a1, a2, a3, vb[jdp][2], vb[jdp][3]);
                    }
                    mmaf16v(o[i][6], a0, a1, a2, a3, vb[3][0], vb[3][1]);
                }
            }
        }
        __syncthreads();   // reads of buf done before next ISSUE overwrites it
    }
    #undef ISSUE_KV

    const int rq = lane >> 2, cq = (lane & 3) * 2;
    #pragma unroll
    for (int i = 0; i < 2; i++) {
        float l0 = __shfl_sync(0xffffffffu, o[i][6][0], lane & 0x1c);
        float l1 = __shfl_sync(0xffffffffu, o[i][6][2], lane & 0x1c);
        float inv0 = 1.0f / l0, inv1 = 1.0f / l1;
        int r0 = tok0 + wm + i * 16 + rq;
        #pragma unroll
        for (int j = 0; j < 6; j++) {
            int col = h * HD + j * 8 + cq;
            *(__half2*)&att16[(size_t)r0 * C_ + col] =
                __floats2half2_rn(o[i][j][0] * inv0, o[i][j][1] * inv0);
            *(__half2*)&att16[(size_t)(r0 + 8) * C_ + col] =
                __floats2half2_rn(o[i][j][2] * inv1, o[i][j][3] * inv1);
        }
    }
}

// ---------------------------------------------------------------------------
// Launch
// ---------------------------------------------------------------------------
#define GEMM_DSM 65536

extern "C" void kernel_launch(void* const* d_in, const int* in_sizes, int n_in,
                              void* d_out, int out_size) {
    const float* x     = (const float*)d_in[0];
    const float* ln1w  = (const float*)d_in[1];
    const float* ln1b  = (const float*)d_in[2];
    const float* qkvw  = (const float*)d_in[3];
    const float* qkvb  = (const float*)d_in[4];
    const float* projw = (const float*)d_in[5];
    const float* projb = (const float*)d_in[6];
    const float* ln2w  = (const float*)d_in[7];
    const float* ln2b  = (const float*)d_in[8];
    const float* fc1w  = (const float*)d_in[9];
    const float* fc1b  = (const float*)d_in[10];
    const float* fc2w  = (const float*)d_in[11];
    const float* fc2b  = (const float*)d_in[12];

    float *x2;
    __half *h16, *qkv16, *att16, *mid16, *w16;
    cudaGetSymbolAddress((void**)&x2,    g_x2);
    cudaGetSymbolAddress((void**)&h16,   g_h16);
    cudaGetSymbolAddress((void**)&qkv16, g_qkv16);
    cudaGetSymbolAddress((void**)&att16, g_att16);
    cudaGetSymbolAddress((void**)&mid16, g_mid16);
    cudaGetSymbolAddress((void**)&w16,   g_w16);

    cudaFuncSetAttribute(gemm16<0,0,1>, cudaFuncAttributeMaxDynamicSharedMemorySize, GEMM_DSM);
    cudaFuncSetAttribute(gemm16<0,0,3>, cudaFuncAttributeMaxDynamicSharedMemorySize, GEMM_DSM);
    cudaFuncSetAttribute(gemm16<1,0,1>, cudaFuncAttributeMaxDynamicSharedMemorySize, GEMM_DSM);
    cudaFuncSetAttribute(gemm16<0,1,2>, cudaFuncAttributeMaxDynamicSharedMemorySize, GEMM_DSM);
    cudaFuncSetAttribute(attn_mma, cudaFuncAttributeMaxDynamicSharedMemorySize, ATTN_DSM);

    // 1. weights fp32 -> fp16
    cvt_all<<<1728, 256>>>(qkvw, projw, fc1w, fc2w, w16);
    // 2. fused transpose + LN1: x -> h16
    transln_k<<<dim3(N_/16, B_), 256>>>(x, ln1w, ln1b, h16);
    // 3. QKV projection (fp16 out)
    gemm16<0,0,1><<<dim3(QKVC/128, M_/128), 256, GEMM_DSM>>>(
        h16, w16 + W_QKV, qkvb, nullptr, nullptr, nullptr, qkv16, M_, QKVC, C_);
    // 4. attention (fp16 out)
    attn_mma<<<dim3(N_/128, B_*NH), 128, ATTN_DSM>>>(qkv16, att16);
    // 5. proj + residual(x, coalesced staged transpose) -> x2 fp32
    gemm16<0,0,3><<<dim3(C_/128, M_/128), 256, GEMM_DSM>>>(
        att16, w16 + W_PROJ, projb, nullptr, x, x2, nullptr, M_, C_, C_);
    // 6. LN2 -> fp16
    ln16_k<<<M_, 128>>>(x2, ln2w, ln2b, h16);
    // 7. fc1 + GELU (fp16 out)
    gemm16<1,0,1><<<dim3(HID/128, M_/128), 256, GEMM_DSM>>>(
        h16, w16 + W_FC1, fc1b, nullptr, nullptr, nullptr, mid16, M_, HID, C_);
    // 8. fc2 + residual(x2), transposed epilogue -> d_out (B,C,N)
    gemm16<0,1,2><<<dim3(C_/128, M_/128), 256, GEMM_DSM>>>(
        mid16, w16 + W_FC2, fc2b, x2, nullptr, (float*)d_out, nullptr, M_, C_, HID);
}

// round 15
// speedup vs baseline: 1.0868x; 1.0500x over previous
#include <cuda_runtime.h>
#include <cuda_fp16.h>
#include <math.h>
#include <stdint.h>

// Problem constants
#define B_   16
#define C_   384
#define N_   1024
#define NH   8
#define HD   48
#define HID  1536
#define M_   (B_*N_)     // 16384 tokens
#define QKVC (3*C_)      // 1152

// ---------------------------------------------------------------------------
// Scratch
// ---------------------------------------------------------------------------
__device__ float  g_x2 [M_*C_];
__device__ __half g_h16 [M_*C_];
__device__ __half g_qkv16[M_*QKVC];
__device__ __half g_att16[M_*C_];
__device__ __half g_mid16[M_*HID];
__device__ __half g_w16[1769472];
#define W_QKV 0
#define W_PROJ 442368
#define W_FC1 589824
#define W_FC2 1179648

// ---------------------------------------------------------------------------
// Helpers
// ---------------------------------------------------------------------------
__device__ __forceinline__ uint32_t smem_u32(const void* p) {
    uint32_t a;
    asm("{ .reg .u64 t; cvta.to.shared.u64 t, %1; cvt.u32.u64 %0, t; }"
        : "=r"(a) : "l"(p));
    return a;
}
#define SW64(o)  ((o) ^ (((o) >> 3) & 0x30))
#define SW128(o) ((o) ^ (((o) >> 3) & 0x70))

__device__ __forceinline__ void ldsm4(uint32_t addr, uint32_t r[4]) {
    asm volatile("ldmatrix.sync.aligned.m8n8.x4.shared.b16 {%0,%1,%2,%3}, [%4];"
                 : "=r"(r[0]), "=r"(r[1]), "=r"(r[2]), "=r"(r[3]) : "r"(addr));
}
__device__ __forceinline__ void ldsm4t(uint32_t addr, uint32_t r[4]) {
    asm volatile("ldmatrix.sync.aligned.m8n8.x4.trans.shared.b16 {%0,%1,%2,%3}, [%4];"
                 : "=r"(r[0]), "=r"(r[1]), "=r"(r[2]), "=r"(r[3]) : "r"(addr));
}
__device__ __forceinline__ void mmaf16(float* c, const uint32_t* a,
                                       uint32_t b0, uint32_t b1) {
    asm volatile("mma.sync.aligned.m16n8k16.row.col.f32.f16.f16.f32 "
                 "{%0,%1,%2,%3}, {%4,%5,%6,%7}, {%8,%9}, {%0,%1,%2,%3};"
                 : "+f"(c[0]), "+f"(c[1]), "+f"(c[2]), "+f"(c[3])
                 : "r"(a[0]), "r"(a[1]), "r"(a[2]), "r"(a[3]), "r"(b0), "r"(b1));
}
__device__ __forceinline__ void mmaf16v(float* c, uint32_t a0, uint32_t a1,
                                        uint32_t a2, uint32_t a3,
                                        uint32_t b0, uint32_t b1) {
    asm volatile("mma.sync.aligned.m16n8k16.row.col.f32.f16.f16.f32 "
                 "{%0,%1,%2,%3}, {%4,%5,%6,%7}, {%8,%9}, {%0,%1,%2,%3};"
                 : "+f"(c[0]), "+f"(c[1]), "+f"(c[2]), "+f"(c[3])
                 : "r"(a0), "r"(a1), "r"(a2), "r"(a3), "r"(b0), "r"(b1));
}
__device__ __forceinline__ void cpasync16(uint32_t s, const void* g) {
    asm volatile("cp.async.cg.shared.global [%0], [%1], 16;" :: "r"(s), "l"(g));
}
__device__ __forceinline__ uint32_t packh2(float x, float y) {
    __half2 t = __floats2half2_rn(x, y);
    return *(uint32_t*)&t;
}
__device__ __forceinline__ uint32_t h2ex2(uint32_t x) {
    uint32_t r;
    asm("ex2.approx.f16x2 %0, %1;" : "=r"(r) : "r"(x));
    return r;
}
__device__ __forceinline__ uint32_t h2mul(uint32_t a, uint32_t b) {
    uint32_t r;
    asm("mul.f16x2 %0, %1, %2;" : "=r"(r) : "r"(a), "r"(b));
    return r;
}

// ---------------------------------------------------------------------------
// All weights fp32 -> fp16 in one launch
// ---------------------------------------------------------------------------
__global__ void cvt_all(const float* __restrict__ qkvw, const float* __restrict__ projw,
                        const float* __restrict__ fc1w, const float* __restrict__ fc2w,
                        __half* __restrict__ w16) {
    int i = blockIdx.x * 256 + threadIdx.x;   // 0 .. 442367
    const float* s;
    __half* d;
    if (i < 110592)      { s = qkvw;  d = w16 + W_QKV;  }
    else if (i < 147456) { s = projw; d = w16 + W_PROJ; i -= 110592; }
    else if (i < 294912) { s = fc1w;  d = w16 + W_FC1;  i -= 147456; }
    else                 { s = fc2w;  d = w16 + W_FC2;  i -= 294912; }
    float4 v = ((const float4*)s)[i];
    __half2* dp = (__half2*)d;
    dp[2 * i]     = __floats2half2_rn(v.x, v.y);
    dp[2 * i + 1] = __floats2half2_rn(v.z, v.w);
}

// ---------------------------------------------------------------------------
// Fused transpose + LayerNorm: x (B,C,N) fp32 -> h16 (B,N,C) fp16
// ---------------------------------------------------------------------------
__global__ __launch_bounds__(256)
void transln_k(const float* __restrict__ x, const float* __restrict__ w,
               const float* __restrict__ bias, __half* __restrict__ Y) {
    __shared__ float fs[384 * 17];
    __shared__ float ps[256], pq[256];
    __shared__ float mrow[16], rrow[16];
    const int b = blockIdx.y, n0 = blockIdx.x * 16;
    const int tok = threadIdx.x & 15, c0 = threadIdx.x >> 4;
    const float* xb = x + (size_t)b * C_ * N_ + n0;
    float s = 0.0f, q = 0.0f;
    #pragma unroll
    for (int i = 0; i < 24; i++) {
        int c = c0 + i * 16;
        float v = xb[(size_t)c * N_ + tok];
        s += v; q += v * v;
        fs[c * 17 + tok] = v;
    }
    ps[c0 * 16 + tok] = s;
    pq[c0 * 16 + tok] = q;
    __syncthreads();
    if (threadIdx.x < 16) {
        float ss = 0.0f, qq = 0.0f;
        #pragma unroll
        for (int j = 0; j < 16; j++) { ss += ps[j * 16 + threadIdx.x]; qq += pq[j * 16 + threadIdx.x]; }
        float mean = ss * (1.0f / C_);
        float var  = qq * (1.0f / C_) - mean * mean;
        mrow[threadIdx.x] = mean;
        rrow[threadIdx.x] = rsqrtf(var + 1e-5f);
    }
    __syncthreads();
    const int tok2 = threadIdx.x >> 4, part = threadIdx.x & 15;
    const float mean = mrow[tok2], rstd = rrow[tok2];
    __half* yr = Y + (size_t)(b * N_ + n0 + tok2) * C_;
    #pragma unroll
    for (int i = 0; i < 24; i++) {
        int c = part + i * 16;
        float v = fs[c * 17 + tok2];
        yr[c] = __float2half((v - mean) * rstd * w[c] + bias[c]);
    }
}

// ---------------------------------------------------------------------------
// LayerNorm (rows of 384) from token-major fp32, fp16 output (LN2)
// ---------------------------------------------------------------------------
__global__ void ln16_k(const float* __restrict__ X, const float* __restrict__ w,
                       const float* __restrict__ bias, __half* __restrict__ Y) {
    int row = blockIdx.x;
    int tid = threadIdx.x;
    const float* xr = X + (size_t)row * C_;
    float v0 = xr[tid], v1 = xr[tid + 128], v2 = xr[tid + 256];
    float s = v0 + v1 + v2;
    float q = v0 * v0 + v1 * v1 + v2 * v2;
    #pragma unroll
    for (int o = 16; o > 0; o >>= 1) {
        s += __shfl_xor_sync(0xffffffffu, s, o);
        q += __shfl_xor_sync(0xffffffffu, q, o);
    }
    __shared__ float ss[4], sq[4];
    int wid = tid >> 5, lane = tid & 31;
    if (lane == 0) { ss[wid] = s; sq[wid] = q; }
    __syncthreads();
    s = ss[0] + ss[1] + ss[2] + ss[3];
    q = sq[0] + sq[1] + sq[2] + sq[3];
    float mean = s * (1.0f / C_);
    float var  = q * (1.0f / C_) - mean * mean;
    float rstd = rsqrtf(var + 1e-5f);
    __half* yr = Y + (size_t)row * C_;
    yr[tid]       = __float2half((v0 - mean) * rstd * w[tid]       + bias[tid]);
    yr[tid + 128] = __float2half((v1 - mean) * rstd * w[tid + 128] + bias[tid + 128]);
    yr[tid + 256] = __float2half((v2 - mean) * rstd * w[tid + 256] + bias[tid + 256]);
}

// ---------------------------------------------------------------------------
// fp16 mma.sync NT GEMM: 128xBN tile (BN = 128 or 64), 256 threads,
// 8 warps (4M x 2N), warp tile 32x(BN/2), k-chunk 32, 3-stage cp.async
// pipeline (R11-proven config, trailing sync), SW64 smem, ldmatrix.x4.
// ACT: 1 = exact GELU.
// RES: 0 none; 1 fp32 token-major (Res); 2 residual = x (B,C,N) read
//      transposed on the fly (Xres).
// OUT: 0 fp32 token-major; 1 fp16 token-major;
//      2 fp32 transposed to (B,C,N) via smem staging (fc2 -> d_out).
// Dynamic smem: 3 stages x (128+BN)*64 bytes.
// ---------------------------------------------------------------------------
template<int BN, int ACT, int RES, int OUT>
__global__ __launch_bounds__(256)
void gemm16(const __half* __restrict__ A, const __half* __restrict__ Bw,
            const float* __restrict__ bias, const float* __restrict__ Res,
            const float* __restrict__ Xres,
            float* __restrict__ Cf, __half* __restrict__ Ch,
            int M, int N, int K) {
    constexpr int STAGE = (128 + BN) * 64;     // bytes per pipeline stage
    constexpr int JT = BN / 16;                // n8 tiles per warp
    constexpr int JP = BN / 32;                // ldsm.x4 B loads per kk
    constexpr int BLD = BN / 64;               // B cp.async iters (256 thr)
    extern __shared__ __align__(128) char dsm[];
    const uint32_t base = smem_u32(dsm);
    const int tid = threadIdx.x, lane = tid & 31, warp = tid >> 5;
    const int wm = (warp & 3) * 32, wn = (warp >> 2) * (BN / 2);
    const int m0 = blockIdx.y * 128, n0 = blockIdx.x * BN;
    const int l8 = lane & 7, sub = lane >> 3;
    const int nc = K >> 5;

    float acc[2][JT][4];
    #pragma unroll
    for (int i = 0; i < 2; i++)
        #pragma unroll
        for (int j = 0; j < JT; j++)
            #pragma unroll
            for (int c = 0; c < 4; c++) acc[i][j][c] = 0.0f;

    #define ISSUE(st, k0)                                                        \
        do {                                                                     \
            _Pragma("unroll")                                                    \
            for (int t = 0; t < 2; t++) {                                        \
                int e = tid + t * 256;                                           \
                int r = e >> 2, cc = e & 3;                                      \
                cpasync16(base + (st) * STAGE + SW64((uint32_t)(r * 64 + cc * 16)), \
                          A + (size_t)(m0 + r) * K + (k0) + cc * 8);             \
            }                                                                    \
            _Pragma("unroll")                                                    \
            for (int t = 0; t < BLD; t++) {                                      \
                int e = tid + t * 256;                                           \
                int r = e >> 2, cc = e & 3;                                      \
                cpasync16(base + (st) * STAGE + 8192 + SW64((uint32_t)(r * 64 + cc * 16)), \
                          Bw + (size_t)(n0 + r) * K + (k0) + cc * 8);            \
            }                                                                    \
            asm volatile("cp.async.commit_group;");                              \
        } while (0)

    ISSUE(0, 0);
    ISSUE(1, 32);

    for (int c = 0; c < nc; c++) {
        const int buf = c % 3;
        if (c + 1 < nc) { asm volatile("cp.async.wait_group 1;"); }
        else            { asm volatile("cp.async.wait_group 0;"); }
        __syncthreads();
        if (c + 2 < nc) ISSUE((c + 2) % 3, (c + 2) * 32);

        const uint32_t aA = base + buf * STAGE;
        const uint32_t aB = aA + 8192;
        #pragma unroll
        for (int kk = 0; kk < 2; kk++) {
            uint32_t af[2][4];
            #pragma unroll
            for (int i = 0; i < 2; i++) {
                uint32_t off = (uint32_t)((wm + i * 16 + (sub & 1) * 8 + l8) * 64
                                          + kk * 32 + (sub >> 1) * 16);
                ldsm4(aA + SW64(off), af[i]);
            }
            #pragma unroll
            for (int jp = 0; jp < JP; jp++) {
                uint32_t bf[4];
                uint32_t off = (uint32_t)((wn + jp * 16 + (sub & 1) * 8 + l8) * 64
                                          + kk * 32 + (sub >> 1) * 16);
                ldsm4(aB + SW64(off), bf);
                #pragma unroll
                for (int i = 0; i < 2; i++) {
                    mmaf16(acc[i][2 * jp],     af[i], bf[0], bf[2]);
                    mmaf16(acc[i][2 * jp + 1], af[i], bf[1], bf[3]);
                }
            }
        }
        __syncthreads();
    }
    #undef ISSUE

    const int rq = lane >> 2, cq = (lane & 3) * 2;

    if (OUT == 2) {
        // staged transpose-out: out[b, col, n]
        float* stage = (float*)dsm;
        const int bb = m0 >> 10;
        const int nbase = m0 & 1023;
        if (BN == 128) {
            // two rounds of 64 cols, stage [128 tokens][65]
            #pragma unroll 1
            for (int halfc = 0; halfc < 2; halfc++) {
                __syncthreads();
                if ((warp >> 2) == halfc) {
                    #pragma unroll
                    for (int i = 0; i < 2; i++)
                        #pragma unroll
                        for (int hrow = 0; hrow < 2; hrow++) {
                            int row_local = wm + i * 16 + rq + hrow * 8;
                            #pragma unroll
                            for (int j = 0; j < JT; j++) {
                                int col_local = j * 8 + cq;
                                int col = n0 + halfc * 64 + col_local;
                                float v0 = acc[i][j][hrow * 2 + 0] + bias[col];
                                float v1 = acc[i][j][hrow * 2 + 1] + bias[col + 1];
                                if (RES == 1) {
                                    float2 r = *(const float2*)&Res[(size_t)(m0 + row_local) * N + col];
                                    v0 += r.x; v1 += r.y;
                                }
                                stage[row_local * 65 + col_local]     = v0;
                                stage[row_local * 65 + col_local + 1] = v1;
                            }
                        }
                }
                __syncthreads();
                #pragma unroll
                for (int it = 0; it < 32; it++) {
                    int idx = tid + it * 256;
                    int cl = idx >> 7, nl = idx & 127;
                    Cf[((size_t)bb * C_ + n0 + halfc * 64 + cl) * N_ + nbase + nl]
                        = stage[nl * 65 + cl];
                }
            }
        } else {
            // BN == 64: one round, all warps stage their 32x32 patch
            __syncthreads();
            #pragma unroll
            for (int i = 0; i < 2; i++)
                #pragma unroll
                for (int hrow = 0; hrow < 2; hrow++) {
                    int row_local = wm + i * 16 + rq + hrow * 8;
                    #pragma unroll
                    for (int j = 0; j < JT; j++) {
                        int col_local = wn + j * 8 + cq;
                        int col = n0 + col_local;
                        float v0 = acc[i][j][hrow * 2 + 0] + bias[col];
                        float v1 = acc[i][j][hrow * 2 + 1] + bias[col + 1];
                        if (RES == 1) {
                            float2 r = *(const float2*)&Res[(size_t)(m0 + row_local) * N + col];
                            v0 += r.x; v1 += r.y;
                        }
                        stage[row_local * 65 + col_local]     = v0;
                        stage[row_local * 65 + col_local + 1] = v1;
                    }
                }
            __syncthreads();
            #pragma unroll
            for (int it = 0; it < 32; it++) {
                int idx = tid + it * 256;      // 0..8191 = 64 cols x 128 tokens
                int cl = idx >> 7, nl = idx & 127;
                Cf[((size_t)bb * C_ + n0 + cl) * N_ + nbase + nl]
                    = stage[nl * 65 + cl];
            }
        }
        return;
    }

    #pragma unroll
    for (int i = 0; i < 2; i++) {
        #pragma unroll
        for (int half = 0; half < 2; half++) {
            int row = m0 + wm + i * 16 + rq + half * 8;
            #pragma unroll
            for (int j = 0; j < JT; j++) {
                int col = n0 + wn + j * 8 + cq;
                size_t off = (size_t)row * N + col;
                float v0 = acc[i][j][half * 2 + 0] + bias[col];
                float v1 = acc[i][j][half * 2 + 1] + bias[col + 1];
                if (ACT == 1) {
                    v0 = 0.5f * v0 * (1.0f + erff(v0 * 0.70710678118654752f));
                    v1 = 0.5f * v1 * (1.0f + erff(v1 * 0.70710678118654752f));
                }
                if (RES == 1) {
                    float2 r = *(const float2*)&Res[off];
                    v0 += r.x; v1 += r.y;
                }
                if (RES == 2) {
                    int bb = row >> 10, nn = row & 1023;
                    v0 += Xres[((size_t)bb * C_ + col)     * N_ + nn];
                    v1 += Xres[((size_t)bb * C_ + col + 1) * N_ + nn];
                }
                if (OUT == 1) {
                    *(__half2*)&Ch[off] = __floats2half2_rn(v0, v1);
                } else {
                    *(float2*)&Cf[off] = make_float2(v0, v1);
                }
            }
        }
    }
}

// ---------------------------------------------------------------------------
// Tensor-core flash attention, cp.async double-buffered K/V (R12, proven).
// exp via ex2.approx.f16x2; row-sum l via ones-column MMA; Q pre-scaled.
// CTA = (b, h, 128-query tile), 128 threads, 2 CTAs/SM.
// dsm layout: Q@0 (16KB) | K0@16K | V0@32K | K1@48K | V1@64K   (80KB)
// ---------------------------------------------------------------------------
#define ATTN_DSM 81920
__global__ __launch_bounds__(128, 2)
void attn_mma(const __half* __restrict__ qkv16, __half* __restrict__ att16) {
    extern __shared__ __align__(128) char dsm[];
    const uint32_t base = smem_u32(dsm);
    const int tid = threadIdx.x, lane = tid & 31, warp = tid >> 5;
    const int bh = blockIdx.y, b = bh >> 3, h = bh & 7;
    const int tok0 = b * N_ + blockIdx.x * 128;
    const float kscale = 0.14433756729740643f * 1.4426950408889634f;  // scale*log2e
    const int l8 = lane & 7, sub = lane >> 3;
    const int wm = warp * 32;

    // Q tile
    {
        const uint4* src = (const uint4*)(qkv16 + (size_t)(tok0 + tid) * QKVC + h * HD);
        #pragma unroll
        for (int j = 0; j < 6; j++)
            *(uint4*)(dsm + SW128((uint32_t)(tid * 128 + j * 16))) = src[j];
    }
    // ones column (col 48 = 1.0, 49..63 = 0) in both V buffers — cp.async only
    // touches byte range [0,96) per row, so these persist.
    #pragma unroll
    for (int bufi = 0; bufi < 2; bufi++) {
        char* vb = dsm + 32768 + bufi * 32768;
        *(uint4*)(vb + SW128((uint32_t)(tid * 128 + 96)))  = make_uint4(0x3C00u, 0, 0, 0);
        *(uint4*)(vb + SW128((uint32_t)(tid * 128 + 112))) = make_uint4(0, 0, 0, 0);
    }

    #define ISSUE_KV(bufi, kt)                                                   \
        do {                                                                     \
            int tk = b * N_ + (kt) * 128 + tid;                                  \
            const __half* kp = qkv16 + (size_t)tk * QKVC + C_     + h * HD;      \
            const __half* vp = qkv16 + (size_t)tk * QKVC + 2 * C_ + h * HD;      \
            uint32_t kb = base + 16384 + (bufi) * 32768;                         \
            _Pragma("unroll")                                                    \
            for (int j = 0; j < 6; j++) {                                        \
                uint32_t so = SW128((uint32_t)(tid * 128 + j * 16));             \
                cpasync16(kb + so,         kp + j * 8);                          \
                cpasync16(kb + 16384 + so, vp + j * 8);                          \
            }                                                                    \
            asm volatile("cp.async.commit_group;");                              \
        } while (0)

    ISSUE_KV(0, 0);
    __syncthreads();   // Q + ones visible

    // Q fragments, pre-scaled by kscale
    const uint32_t ksc2 = packh2(kscale, kscale);
    uint32_t qa[2][3][4];
    #pragma unroll
    for (int i = 0; i < 2; i++)
        #pragma unroll
        for (int ks = 0; ks < 3; ks++) {
            uint32_t off = (uint32_t)((wm + i * 16 + (sub & 1) * 8 + l8) * 128
                                      + ks * 32 + (sub >> 1) * 16);
            ldsm4(base + SW128(off), qa[i][ks]);
            #pragma unroll
            for (int q = 0; q < 4; q++) qa[i][ks][q] = h2mul(qa[i][ks][q], ksc2);
        }

    float o[2][7][4];
    #pragma unroll
    for (int i = 0; i < 2; i++)
        #pragma unroll
        for (int j = 0; j < 7; j++)
            #pragma unroll
            for (int c = 0; c < 4; c++) o[i][j][c] = 0.0f;

    for (int kt = 0; kt < 8; kt++) {
        const int buf = kt & 1;
        if (kt + 1 < 8) {
            ISSUE_KV(buf ^ 1, kt + 1);
            asm volatile("cp.async.wait_group 1;");
        } else {
            asm volatile("cp.async.wait_group 0;");
        }
        __syncthreads();

        const uint32_t aK = base + 16384 + buf * 32768;
        const uint32_t aV = aK + 16384;

        #pragma unroll
        for (int kh = 0; kh < 2; kh++) {
            float s[2][8][4];
            #pragma unroll
            for (int i = 0; i < 2; i++)
                #pragma unroll
                for (int j = 0; j < 8; j++)
                    #pragma unroll
                    for (int c = 0; c < 4; c++) s[i][j][c] = 0.0f;

            #pragma unroll
            for (int ks = 0; ks < 3; ks++) {
                #pragma unroll
                for (int jp = 0; jp < 4; jp++) {
                    uint32_t bf[4];
                    uint32_t off = (uint32_t)((kh * 64 + jp * 16 + (sub & 1) * 8 + l8) * 128
                                              + ks * 32 + (sub >> 1) * 16);
                    ldsm4(aK + SW128(off), bf);
                    #pragma unroll
                    for (int i = 0; i < 2; i++) {
                        mmaf16(s[i][2 * jp],     qa[i][ks], bf[0], bf[2]);
                        mmaf16(s[i][2 * jp + 1], qa[i][ks], bf[1], bf[3]);
                    }
                }
            }

            uint32_t ph[2][8][2];
            #pragma unroll
            for (int i = 0; i < 2; i++)
                #pragma unroll
                for (int j = 0; j < 8; j++) {
                    ph[i][j][0] = h2ex2(packh2(s[i][j][0], s[i][j][1]));
                    ph[i][j][1] = h2ex2(packh2(s[i][j][2], s[i][j][3]));
                }

            #pragma unroll
            for (int t = 0; t < 4; t++) {
                uint32_t vb[4][4];
                #pragma unroll
                for (int jdp = 0; jdp < 4; jdp++) {
                    uint32_t off = (uint32_t)((kh * 64 + t * 16 + (sub & 1) * 8 + l8) * 128
                                              + jdp * 32 + (sub >> 1) * 16);
                    ldsm4t(aV + SW128(off), vb[jdp]);
                }
                #pragma unroll
                for (int i = 0; i < 2; i++) {
                    uint32_t a0 = ph[i][2 * t][0],     a1 = ph[i][2 * t][1];
                    uint32_t a2 = ph[i][2 * t + 1][0], a3 = ph[i][2 * t + 1][1];
                    #pragma unroll
                    for (int jdp = 0; jdp < 3; jdp++) {
                        mmaf16v(o[i][2 * jdp],     a0, a1, a2, a3, vb[jdp][0], vb[jdp][1]);
                        mmaf16v(o[i][2 * jdp + 1], a0, a1, a2, a3, vb[jdp][2], vb[jdp][3]);
                    }
                    mmaf16v(o[i][6], a0, a1, a2, a3, vb[3][0], vb[3][1]);
                }
            }
        }
        __syncthreads();   // reads of buf done before next ISSUE overwrites it
    }
    #undef ISSUE_KV

    const int rq = lane >> 2, cq = (lane & 3) * 2;
    #pragma unroll
    for (int i = 0; i < 2; i++) {
        float l0 = __shfl_sync(0xffffffffu, o[i][6][0], lane & 0x1c);
        float l1 = __shfl_sync(0xffffffffu, o[i][6][2], lane & 0x1c);
        float inv0 = 1.0f / l0, inv1 = 1.0f / l1;
        int r0 = tok0 + wm + i * 16 + rq;
        #pragma unroll
        for (int j = 0; j < 6; j++) {
            int col = h * HD + j * 8 + cq;
            *(__half2*)&att16[(size_t)r0 * C_ + col] =
                __floats2half2_rn(o[i][j][0] * inv0, o[i][j][1] * inv0);
            *(__half2*)&att16[(size_t)(r0 + 8) * C_ + col] =
                __floats2half2_rn(o[i][j][2] * inv1, o[i][j][3] * inv1);
        }
    }
}

// ---------------------------------------------------------------------------
// Launch
// ---------------------------------------------------------------------------
#define DSM_BN128 49152   // 3 stages x 16KB
#define DSM_BN64  36864   // 3 stages x 12KB (>= 128x65x4 stage for OUT=2)

extern "C" void kernel_launch(void* const* d_in, const int* in_sizes, int n_in,
                              void* d_out, int out_size) {
    const float* x     = (const float*)d_in[0];
    const float* ln1w  = (const float*)d_in[1];
    const float* ln1b  = (const float*)d_in[2];
    const float* qkvw  = (const float*)d_in[3];
    const float* qkvb  = (const float*)d_in[4];
    const float* projw = (const float*)d_in[5];
    const float* projb = (const float*)d_in[6];
    const float* ln2w  = (const float*)d_in[7];
    const float* ln2b  = (const float*)d_in[8];
    const float* fc1w  = (const float*)d_in[9];
    const float* fc1b  = (const float*)d_in[10];
    const float* fc2w  = (const float*)d_in[11];
    const float* fc2b  = (const float*)d_in[12];

    float *x2;
    __half *h16, *qkv16, *att16, *mid16, *w16;
    cudaGetSymbolAddress((void**)&x2,    g_x2);
    cudaGetSymbolAddress((void**)&h16,   g_h16);
    cudaGetSymbolAddress((void**)&qkv16, g_qkv16);
    cudaGetSymbolAddress((void**)&att16, g_att16);
    cudaGetSymbolAddress((void**)&mid16, g_mid16);
    cudaGetSymbolAddress((void**)&w16,   g_w16);

    cudaFuncSetAttribute(gemm16<128,0,0,1>, cudaFuncAttributeMaxDynamicSharedMemorySize, DSM_BN128);
    cudaFuncSetAttribute(gemm16<64,0,2,0>,  cudaFuncAttributeMaxDynamicSharedMemorySize, DSM_BN64);
    cudaFuncSetAttribute(gemm16<128,1,0,1>, cudaFuncAttributeMaxDynamicSharedMemorySize, DSM_BN128);
    cudaFuncSetAttribute(gemm16<64,0,1,2>,  cudaFuncAttributeMaxDynamicSharedMemorySize, DSM_BN64);
    cudaFuncSetAttribute(attn_mma, cudaFuncAttributeMaxDynamicSharedMemorySize, ATTN_DSM);

    // 1. weights fp32 -> fp16
    cvt_all<<<1728, 256>>>(qkvw, projw, fc1w, fc2w, w16);
    // 2. fused transpose + LN1: x -> h16
    transln_k<<<dim3(N_/16, B_), 256>>>(x, ln1w, ln1b, h16);
    // 3. QKV projection (fp16 out), BN=128
    gemm16<128,0,0,1><<<dim3(QKVC/128, M_/128), 256, DSM_BN128>>>(
        h16, w16 + W_QKV, qkvb, nullptr, nullptr, nullptr, qkv16, M_, QKVC, C_);
    // 4. attention (fp16 out)
    attn_mma<<<dim3(N_/128, B_*NH), 128, ATTN_DSM>>>(qkv16, att16);
    // 5. proj + residual(x, transposed on the fly) -> x2 fp32, BN=64
    gemm16<64,0,2,0><<<dim3(C_/64, M_/128), 256, DSM_BN64>>>(
        att16, w16 + W_PROJ, projb, nullptr, x, x2, nullptr, M_, C_, C_);
    // 6. LN2 -> fp16
    ln16_k<<<M_, 128>>>(x2, ln2w, ln2b, h16);
    // 7. fc1 + GELU (fp16 out), BN=128
    gemm16<128,1,0,1><<<dim3(HID/128, M_/128), 256, DSM_BN128>>>(
        h16, w16 + W_FC1, fc1b, nullptr, nullptr, nullptr, mid16, M_, HID, C_);
    // 8. fc2 + residual(x2), transposed epilogue -> d_out (B,C,N), BN=64
    gemm16<64,0,1,2><<<dim3(C_/64, M_/128), 256, DSM_BN64>>>(
        mid16, w16 + W_FC2, fc2b, x2, nullptr, (float*)d_out, nullptr, M_, C_, HID);
}

// round 16
// speedup vs baseline: 1.0983x; 1.0106x over previous
#include <cuda_runtime.h>
#include <cuda_fp16.h>
#include <math.h>
#include <stdint.h>

// Problem constants
#define B_   16
#define C_   384
#define N_   1024
#define NH   8
#define HD   48
#define HID  1536
#define M_   (B_*N_)     // 16384 tokens
#define QKVC (3*C_)      // 1152

// ---------------------------------------------------------------------------
// Scratch
// ---------------------------------------------------------------------------
__device__ float  g_x2 [M_*C_];
__device__ __half g_h16 [M_*C_];
__device__ __half g_qkv16[M_*QKVC];
__device__ __half g_att16[M_*C_];
__device__ __half g_mid16[M_*HID];
__device__ __half g_w16[1769472];
#define W_QKV 0
#define W_PROJ 442368
#define W_FC1 589824
#define W_FC2 1179648

// ---------------------------------------------------------------------------
// Helpers
// ---------------------------------------------------------------------------
__device__ __forceinline__ uint32_t smem_u32(const void* p) {
    uint32_t a;
    asm("{ .reg .u64 t; cvta.to.shared.u64 t, %1; cvt.u32.u64 %0, t; }"
        : "=r"(a) : "l"(p));
    return a;
}
#define SW64(o)  ((o) ^ (((o) >> 3) & 0x30))

__device__ __forceinline__ void ldsm4(uint32_t addr, uint32_t r[4]) {
    asm volatile("ldmatrix.sync.aligned.m8n8.x4.shared.b16 {%0,%1,%2,%3}, [%4];"
                 : "=r"(r[0]), "=r"(r[1]), "=r"(r[2]), "=r"(r[3]) : "r"(addr));
}
__device__ __forceinline__ void ldsm4t(uint32_t addr, uint32_t r[4]) {
    asm volatile("ldmatrix.sync.aligned.m8n8.x4.trans.shared.b16 {%0,%1,%2,%3}, [%4];"
                 : "=r"(r[0]), "=r"(r[1]), "=r"(r[2]), "=r"(r[3]) : "r"(addr));
}
__device__ __forceinline__ void ldsm2t(uint32_t addr, uint32_t r[2]) {
    asm volatile("ldmatrix.sync.aligned.m8n8.x2.trans.shared.b16 {%0,%1}, [%2];"
                 : "=r"(r[0]), "=r"(r[1]) : "r"(addr));
}
__device__ __forceinline__ void mmaf16(float* c, const uint32_t* a,
                                       uint32_t b0, uint32_t b1) {
    asm volatile("mma.sync.aligned.m16n8k16.row.col.f32.f16.f16.f32 "
                 "{%0,%1,%2,%3}, {%4,%5,%6,%7}, {%8,%9}, {%0,%1,%2,%3};"
                 : "+f"(c[0]), "+f"(c[1]), "+f"(c[2]), "+f"(c[3])
                 : "r"(a[0]), "r"(a[1]), "r"(a[2]), "r"(a[3]), "r"(b0), "r"(b1));
}
__device__ __forceinline__ void mmaf16v(float* c, uint32_t a0, uint32_t a1,
                                        uint32_t a2, uint32_t a3,
                                        uint32_t b0, uint32_t b1) {
    asm volatile("mma.sync.aligned.m16n8k16.row.col.f32.f16.f16.f32 "
                 "{%0,%1,%2,%3}, {%4,%5,%6,%7}, {%8,%9}, {%0,%1,%2,%3};"
                 : "+f"(c[0]), "+f"(c[1]), "+f"(c[2]), "+f"(c[3])
                 : "r"(a0), "r"(a1), "r"(a2), "r"(a3), "r"(b0), "r"(b1));
}
// fp16-accumulator MMA for S = QK^T (output packed f16x2, A-fragment layout)
__device__ __forceinline__ void mmah16(uint32_t* c, const uint32_t* a,
                                       uint32_t b0, uint32_t b1) {
    asm volatile("mma.sync.aligned.m16n8k16.row.col.f16.f16.f16.f16 "
                 "{%0,%1}, {%2,%3,%4,%5}, {%6,%7}, {%0,%1};"
                 : "+r"(c[0]), "+r"(c[1])
                 : "r"(a[0]), "r"(a[1]), "r"(a[2]), "r"(a[3]), "r"(b0), "r"(b1));
}
__device__ __forceinline__ void cpasync16(uint32_t s, const void* g) {
    asm volatile("cp.async.cg.shared.global [%0], [%1], 16;" :: "r"(s), "l"(g));
}
__device__ __forceinline__ uint32_t packh2(float x, float y) {
    __half2 t = __floats2half2_rn(x, y);
    return *(uint32_t*)&t;
}
__device__ __forceinline__ uint32_t h2ex2(uint32_t x) {
    uint32_t r;
    asm("ex2.approx.f16x2 %0, %1;" : "=r"(r) : "r"(x));
    return r;
}
__device__ __forceinline__ uint32_t h2mul(uint32_t a, uint32_t b) {
    uint32_t r;
    asm("mul.f16x2 %0, %1, %2;" : "=r"(r) : "r"(a), "r"(b));
    return r;
}

// ---------------------------------------------------------------------------
// All weights fp32 -> fp16 in one launch
// ---------------------------------------------------------------------------
__global__ void cvt_all(const float* __restrict__ qkvw, const float* __restrict__ projw,
                        const float* __restrict__ fc1w, const float* __restrict__ fc2w,
                        __half* __restrict__ w16) {
    int i = blockIdx.x * 256 + threadIdx.x;   // 0 .. 442367
    const float* s;
    __half* d;
    if (i < 110592)      { s = qkvw;  d = w16 + W_QKV;  }
    else if (i < 147456) { s = projw; d = w16 + W_PROJ; i -= 110592; }
    else if (i < 294912) { s = fc1w;  d = w16 + W_FC1;  i -= 147456; }
    else                 { s = fc2w;  d = w16 + W_FC2;  i -= 294912; }
    float4 v = ((const float4*)s)[i];
    __half2* dp = (__half2*)d;
    dp[2 * i]     = __floats2half2_rn(v.x, v.y);
    dp[2 * i + 1] = __floats2half2_rn(v.z, v.w);
}

// ---------------------------------------------------------------------------
// Fused transpose + LayerNorm: x (B,C,N) fp32 -> h16 (B,N,C) fp16
// ---------------------------------------------------------------------------
__global__ __launch_bounds__(256)
void transln_k(const float* __restrict__ x, const float* __restrict__ w,
               const float* __restrict__ bias, __half* __restrict__ Y) {
    __shared__ float fs[384 * 17];
    __shared__ float ps[256], pq[256];
    __shared__ float mrow[16], rrow[16];
    const int b = blockIdx.y, n0 = blockIdx.x * 16;
    const int tok = threadIdx.x & 15, c0 = threadIdx.x >> 4;
    const float* xb = x + (size_t)b * C_ * N_ + n0;
    float s = 0.0f, q = 0.0f;
    #pragma unroll
    for (int i = 0; i < 24; i++) {
        int c = c0 + i * 16;
        float v = xb[(size_t)c * N_ + tok];
        s += v; q += v * v;
        fs[c * 17 + tok] = v;
    }
    ps[c0 * 16 + tok] = s;
    pq[c0 * 16 + tok] = q;
    __syncthreads();
    if (threadIdx.x < 16) {
        float ss = 0.0f, qq = 0.0f;
        #pragma unroll
        for (int j = 0; j < 16; j++) { ss += ps[j * 16 + threadIdx.x]; qq += pq[j * 16 + threadIdx.x]; }
        float mean = ss * (1.0f / C_);
        float var  = qq * (1.0f / C_) - mean * mean;
        mrow[threadIdx.x] = mean;
        rrow[threadIdx.x] = rsqrtf(var + 1e-5f);
    }
    __syncthreads();
    const int tok2 = threadIdx.x >> 4, part = threadIdx.x & 15;
    const float mean = mrow[tok2], rstd = rrow[tok2];
    __half* yr = Y + (size_t)(b * N_ + n0 + tok2) * C_;
    #pragma unroll
    for (int i = 0; i < 24; i++) {
        int c = part + i * 16;
        float v = fs[c * 17 + tok2];
        yr[c] = __float2half((v - mean) * rstd * w[c] + bias[c]);
    }
}

// ---------------------------------------------------------------------------
// LayerNorm (rows of 384) from token-major fp32, fp16 output (LN2)
// ---------------------------------------------------------------------------
__global__ void ln16_k(const float* __restrict__ X, const float* __restrict__ w,
                       const float* __restrict__ bias, __half* __restrict__ Y) {
    int row = blockIdx.x;
    int tid = threadIdx.x;
    const float* xr = X + (size_t)row * C_;
    float v0 = xr[tid], v1 = xr[tid + 128], v2 = xr[tid + 256];
    float s = v0 + v1 + v2;
    float q = v0 * v0 + v1 * v1 + v2 * v2;
    #pragma unroll
    for (int o = 16; o > 0; o >>= 1) {
        s += __shfl_xor_sync(0xffffffffu, s, o);
        q += __shfl_xor_sync(0xffffffffu, q, o);
    }
    __shared__ float ss[4], sq[4];
    int wid = tid >> 5, lane = tid & 31;
    if (lane == 0) { ss[wid] = s; sq[wid] = q; }
    __syncthreads();
    s = ss[0] + ss[1] + ss[2] + ss[3];
    q = sq[0] + sq[1] + sq[2] + sq[3];
    float mean = s * (1.0f / C_);
    float var  = q * (1.0f / C_) - mean * mean;
    float rstd = rsqrtf(var + 1e-5f);
    __half* yr = Y + (size_t)row * C_;
    yr[tid]       = __float2half((v0 - mean) * rstd * w[tid]       + bias[tid]);
    yr[tid + 128] = __float2half((v1 - mean) * rstd * w[tid + 128] + bias[tid + 128]);
    yr[tid + 256] = __float2half((v2 - mean) * rstd * w[tid + 256] + bias[tid + 256]);
}

// ---------------------------------------------------------------------------
// fp16 mma.sync NT GEMM — unchanged from R15 (proven config).
// 128xBN tile (BN = 128 or 64), 256 threads, 3-stage cp.async, SW64 smem.
// ---------------------------------------------------------------------------
template<int BN, int ACT, int RES, int OUT>
__global__ __launch_bounds__(256)
void gemm16(const __half* __restrict__ A, const __half* __restrict__ Bw,
            const float* __restrict__ bias, const float* __restrict__ Res,
            const float* __restrict__ Xres,
            float* __restrict__ Cf, __half* __restrict__ Ch,
            int M, int N, int K) {
    constexpr int STAGE = (128 + BN) * 64;
    constexpr int JT = BN / 16;
    constexpr int JP = BN / 32;
    constexpr int BLD = BN / 64;
    extern __shared__ __align__(128) char dsm[];
    const uint32_t base = smem_u32(dsm);
    const int tid = threadIdx.x, lane = tid & 31, warp = tid >> 5;
    const int wm = (warp & 3) * 32, wn = (warp >> 2) * (BN / 2);
    const int m0 = blockIdx.y * 128, n0 = blockIdx.x * BN;
    const int l8 = lane & 7, sub = lane >> 3;
    const int nc = K >> 5;

    float acc[2][JT][4];
    #pragma unroll
    for (int i = 0; i < 2; i++)
        #pragma unroll
        for (int j = 0; j < JT; j++)
            #pragma unroll
            for (int c = 0; c < 4; c++) acc[i][j][c] = 0.0f;

    #define ISSUE(st, k0)                                                        \
        do {                                                                     \
            _Pragma("unroll")                                                    \
            for (int t = 0; t < 2; t++) {                                        \
                int e = tid + t * 256;                                           \
                int r = e >> 2, cc = e & 3;                                      \
                cpasync16(base + (st) * STAGE + SW64((uint32_t)(r * 64 + cc * 16)), \
                          A + (size_t)(m0 + r) * K + (k0) + cc * 8);             \
            }                                                                    \
            _Pragma("unroll")                                                    \
            for (int t = 0; t < BLD; t++) {                                      \
                int e = tid + t * 256;                                           \
                int r = e >> 2, cc = e & 3;                                      \
                cpasync16(base + (st) * STAGE + 8192 + SW64((uint32_t)(r * 64 + cc * 16)), \
                          Bw + (size_t)(n0 + r) * K + (k0) + cc * 8);            \
            }                                                                    \
            asm volatile("cp.async.commit_group;");                              \
        } while (0)

    ISSUE(0, 0);
    ISSUE(1, 32);

    for (int c = 0; c < nc; c++) {
        const int buf = c % 3;
        if (c + 1 < nc) { asm volatile("cp.async.wait_group 1;"); }
        else            { asm volatile("cp.async.wait_group 0;"); }
        __syncthreads();
        if (c + 2 < nc) ISSUE((c + 2) % 3, (c + 2) * 32);

        const uint32_t aA = base + buf * STAGE;
        const uint32_t aB = aA + 8192;
        #pragma unroll
        for (int kk = 0; kk < 2; kk++) {
            uint32_t af[2][4];
            #pragma unroll
            for (int i = 0; i < 2; i++) {
                uint32_t off = (uint32_t)((wm + i * 16 + (sub & 1) * 8 + l8) * 64
                                          + kk * 32 + (sub >> 1) * 16);
                ldsm4(aA + SW64(off), af[i]);
            }
            #pragma unroll
            for (int jp = 0; jp < JP; jp++) {
                uint32_t bf[4];
                uint32_t off = (uint32_t)((wn + jp * 16 + (sub & 1) * 8 + l8) * 64
                                          + kk * 32 + (sub >> 1) * 16);
                ldsm4(aB + SW64(off), bf);
                #pragma unroll
                for (int i = 0; i < 2; i++) {
                    mmaf16(acc[i][2 * jp],     af[i], bf[0], bf[2]);
                    mmaf16(acc[i][2 * jp + 1], af[i], bf[1], bf[3]);
                }
            }
        }
        __syncthreads();
    }
    #undef ISSUE

    const int rq = lane >> 2, cq = (lane & 3) * 2;

    if (OUT == 2) {
        float* stage = (float*)dsm;
        const int bb = m0 >> 10;
        const int nbase = m0 & 1023;
        if (BN == 128) {
            #pragma unroll 1
            for (int halfc = 0; halfc < 2; halfc++) {
                __syncthreads();
                if ((warp >> 2) == halfc) {
                    #pragma unroll
                    for (int i = 0; i < 2; i++)
                        #pragma unroll
                        for (int hrow = 0; hrow < 2; hrow++) {
                            int row_local = wm + i * 16 + rq + hrow * 8;
                            #pragma unroll
                            for (int j = 0; j < JT; j++) {
                                int col_local = j * 8 + cq;
                                int col = n0 + halfc * 64 + col_local;
                                float v0 = acc[i][j][hrow * 2 + 0] + bias[col];
                                float v1 = acc[i][j][hrow * 2 + 1] + bias[col + 1];
                                if (RES == 1) {
                                    float2 r = *(const float2*)&Res[(size_t)(m0 + row_local) * N + col];
                                    v0 += r.x; v1 += r.y;
                                }
                                stage[row_local * 65 + col_local]     = v0;
                                stage[row_local * 65 + col_local + 1] = v1;
                            }
                        }
                }
                __syncthreads();
                #pragma unroll
                for (int it = 0; it < 32; it++) {
                    int idx = tid + it * 256;
                    int cl = idx >> 7, nl = idx & 127;
                    Cf[((size_t)bb * C_ + n0 + halfc * 64 + cl) * N_ + nbase + nl]
                        = stage[nl * 65 + cl];
                }
            }
        } else {
            __syncthreads();
            #pragma unroll
            for (int i = 0; i < 2; i++)
                #pragma unroll
                for (int hrow = 0; hrow < 2; hrow++) {
                    int row_local = wm + i * 16 + rq + hrow * 8;
                    #pragma unroll
                    for (int j = 0; j < JT; j++) {
                        int col_local = wn + j * 8 + cq;
                        int col = n0 + col_local;
                        float v0 = acc[i][j][hrow * 2 + 0] + bias[col];
                        float v1 = acc[i][j][hrow * 2 + 1] + bias[col + 1];
                        if (RES == 1) {
                            float2 r = *(const float2*)&Res[(size_t)(m0 + row_local) * N + col];
                            v0 += r.x; v1 += r.y;
                        }
                        stage[row_local * 65 + col_local]     = v0;
                        stage[row_local * 65 + col_local + 1] = v1;
                    }
                }
            __syncthreads();
            #pragma unroll
            for (int it = 0; it < 32; it++) {
                int idx = tid + it * 256;
                int cl = idx >> 7, nl = idx & 127;
                Cf[((size_t)bb * C_ + n0 + cl) * N_ + nbase + nl]
                    = stage[nl * 65 + cl];
            }
        }
        return;
    }

    #pragma unroll
    for (int i = 0; i < 2; i++) {
        #pragma unroll
        for (int half = 0; half < 2; half++) {
            int row = m0 + wm + i * 16 + rq + half * 8;
            #pragma unroll
            for (int j = 0; j < JT; j++) {
                int col = n0 + wn + j * 8 + cq;
                size_t off = (size_t)row * N + col;
                float v0 = acc[i][j][half * 2 + 0] + bias[col];
                float v1 = acc[i][j][half * 2 + 1] + bias[col + 1];
                if (ACT == 1) {
                    v0 = 0.5f * v0 * (1.0f + erff(v0 * 0.70710678118654752f));
                    v1 = 0.5f * v1 * (1.0f + erff(v1 * 0.70710678118654752f));
                }
                if (RES == 1) {
                    float2 r = *(const float2*)&Res[off];
                    v0 += r.x; v1 += r.y;
                }
                if (RES == 2) {
                    int bb = row >> 10, nn = row & 1023;
                    v0 += Xres[((size_t)bb * C_ + col)     * N_ + nn];
                    v1 += Xres[((size_t)bb * C_ + col + 1) * N_ + nn];
                }
                if (OUT == 1) {
                    *(__half2*)&Ch[off] = __floats2half2_rn(v0, v1);
                } else {
                    *(float2*)&Cf[off] = make_float2(v0, v1);
                }
            }
        }
    }
}

// ---------------------------------------------------------------------------
// Tensor-core flash attention v2:
//  - S-MMA with fp16 accumulators (no packh2; S lands in A-fragment layout)
//  - pitch-112 unswizzled smem tiles (ldmatrix per-lane row addresses)
//  - 3 CTAs/SM (regs<=170, dsm 70KB)
// CTA = (b, h, 128-query tile), 128 threads.
// dsm: Q@0 (14336) | K0@14336 | V0@28672 | K1@43008 | V1@57344  (71680)
// ---------------------------------------------------------------------------
#define PITCH 112
#define ATTN_DSM 71680
__global__ __launch_bounds__(128, 3)
void attn_mma(const __half* __restrict__ qkv16, __half* __restrict__ att16) {
    extern __shared__ __align__(128) char dsm[];
    const uint32_t base = smem_u32(dsm);
    const int tid = threadIdx.x, lane = tid & 31, warp = tid >> 5;
    const int bh = blockIdx.y, b = bh >> 3, h = bh & 7;
    const int tok0 = b * N_ + blockIdx.x * 128;
    const float kscale = 0.14433756729740643f * 1.4426950408889634f;  // scale*log2e
    const int l8 = lane & 7, sub = lane >> 3;
    const int wm = warp * 32;

    // Q tile (pitch 112)
    {
        const uint4* src = (const uint4*)(qkv16 + (size_t)(tok0 + tid) * QKVC + h * HD);
        #pragma unroll
        for (int j = 0; j < 6; j++)
            *(uint4*)(dsm + tid * PITCH + j * 16) = src[j];
    }
    // ones column (col 48 = 1.0h, cols 49..55 = 0) in both V buffers
    #pragma unroll
    for (int bufi = 0; bufi < 2; bufi++) {
        char* vb = dsm + 28672 + bufi * 28672;
        *(uint4*)(vb + tid * PITCH + 96) = make_uint4(0x3C00u, 0, 0, 0);
    }

    #define ISSUE_KV(bufi, kt)                                                   \
        do {                                                                     \
            int tk = b * N_ + (kt) * 128 + tid;                                  \
            const __half* kp = qkv16 + (size_t)tk * QKVC + C_     + h * HD;      \
            const __half* vp = qkv16 + (size_t)tk * QKVC + 2 * C_ + h * HD;      \
            uint32_t kb = base + 14336 + (bufi) * 28672;                         \
            _Pragma("unroll")                                                    \
            for (int j = 0; j < 6; j++) {                                        \
                cpasync16(kb + tid * PITCH + j * 16,         kp + j * 8);        \
                cpasync16(kb + 14336 + tid * PITCH + j * 16, vp + j * 8);        \
            }                                                                    \
            asm volatile("cp.async.commit_group;");                              \
        } while (0)

    ISSUE_KV(0, 0);
    __syncthreads();   // Q + ones visible

    // Q fragments, pre-scaled by kscale (fp16)
    const uint32_t ksc2 = packh2(kscale, kscale);
    uint32_t qa[2][3][4];
    #pragma unroll
    for (int i = 0; i < 2; i++)
        #pragma unroll
        for (int ks = 0; ks < 3; ks++) {
            uint32_t off = (uint32_t)((wm + i * 16 + (sub & 1) * 8 + l8) * PITCH
                                      + ks * 32 + (sub >> 1) * 16);
            ldsm4(base + off, qa[i][ks]);
            #pragma unroll
            for (int q = 0; q < 4; q++) qa[i][ks][q] = h2mul(qa[i][ks][q], ksc2);
        }

    float o[2][7][4];
    #pragma unroll
    for (int i = 0; i < 2; i++)
        #pragma unroll
        for (int j = 0; j < 7; j++)
            #pragma unroll
            for (int c = 0; c < 4; c++) o[i][j][c] = 0.0f;

    for (int kt = 0; kt < 8; kt++) {
        const int buf = kt & 1;
        if (kt + 1 < 8) {
            ISSUE_KV(buf ^ 1, kt + 1);
            asm volatile("cp.async.wait_group 1;");
        } else {
            asm volatile("cp.async.wait_group 0;");
        }
        __syncthreads();

        const uint32_t aK = base + 14336 + buf * 28672;
        const uint32_t aV = aK + 14336;

        #pragma unroll
        for (int kh = 0; kh < 2; kh++) {
            // S = QK^T, fp16 accumulators (packed; exact A-fragment layout)
            uint32_t s16[2][8][2];
            #pragma unroll
            for (int i = 0; i < 2; i++)
                #pragma unroll
                for (int j = 0; j < 8; j++) { s16[i][j][0] = 0u; s16[i][j][1] = 0u; }

            #pragma unroll
            for (int ks = 0; ks < 3; ks++) {
                #pragma unroll
                for (int jp = 0; jp < 4; jp++) {
                    uint32_t bf[4];
                    uint32_t off = (uint32_t)((kh * 64 + jp * 16 + (sub & 1) * 8 + l8) * PITCH
                                              + ks * 32 + (sub >> 1) * 16);
                    ldsm4(aK + off, bf);
                    #pragma unroll
                    for (int i = 0; i < 2; i++) {
                        mmah16(s16[i][2 * jp],     qa[i][ks], bf[0], bf[2]);
                        mmah16(s16[i][2 * jp + 1], qa[i][ks], bf[1], bf[3]);
                    }
                }
            }

            // P = 2^S in place (Q pre-scaled; softmax shift-invariant exact)
            #pragma unroll
            for (int i = 0; i < 2; i++)
                #pragma unroll
                for (int j = 0; j < 8; j++) {
                    s16[i][j][0] = h2ex2(s16[i][j][0]);
                    s16[i][j][1] = h2ex2(s16[i][j][1]);
                }

            // O += P V ; l accumulates in col 48 (ones column)
            #pragma unroll
            for (int t = 0; t < 4; t++) {
                uint32_t vrow = (uint32_t)((kh * 64 + t * 16 + (sub & 1) * 8 + l8) * PITCH);
                uint32_t vb3[3][4];
                #pragma unroll
                for (int jdp = 0; jdp < 3; jdp++)
                    ldsm4t(aV + vrow + jdp * 32 + (sub >> 1) * 16, vb3[jdp]);
                uint32_t vo[2];
                ldsm2t(aV + vrow + 96, vo);
                #pragma unroll
                for (int i = 0; i < 2; i++) {
                    uint32_t a0 = s16[i][2 * t][0],     a1 = s16[i][2 * t][1];
                    uint32_t a2 = s16[i][2 * t + 1][0], a3 = s16[i][2 * t + 1][1];
                    #pragma unroll
                    for (int jdp = 0; jdp < 3; jdp++) {
                        mmaf16v(o[i][2 * jdp],     a0, a1, a2, a3, vb3[jdp][0], vb3[jdp][1]);
                        mmaf16v(o[i][2 * jdp + 1], a0, a1, a2, a3, vb3[jdp][2], vb3[jdp][3]);
                    }
                    mmaf16v(o[i][6], a0, a1, a2, a3, vo[0], vo[1]);
                }
            }
        }
        __syncthreads();   // reads of buf done before next ISSUE overwrites it
    }
    #undef ISSUE_KV

    const int rq = lane >> 2, cq = (lane & 3) * 2;
    #pragma unroll
    for (int i = 0; i < 2; i++) {
        float l0 = __shfl_sync(0xffffffffu, o[i][6][0], lane & 0x1c);
        float l1 = __shfl_sync(0xffffffffu, o[i][6][2], lane & 0x1c);
        float inv0 = 1.0f / l0, inv1 = 1.0f / l1;
        int r0 = tok0 + wm + i * 16 + rq;
        #pragma unroll
        for (int j = 0; j < 6; j++) {
            int col = h * HD + j * 8 + cq;
            *(__half2*)&att16[(size_t)r0 * C_ + col] =
                __floats2half2_rn(o[i][j][0] * inv0, o[i][j][1] * inv0);
            *(__half2*)&att16[(size_t)(r0 + 8) * C_ + col] =
                __floats2half2_rn(o[i][j][2] * inv1, o[i][j][3] * inv1);
        }
    }
}

// ---------------------------------------------------------------------------
// Launch
// ---------------------------------------------------------------------------
#define DSM_BN128 49152   // 3 stages x 16KB
#define DSM_BN64  36864   // 3 stages x 12KB

extern "C" void kernel_launch(void* const* d_in, const int* in_sizes, int n_in,
                              void* d_out, int out_size) {
    const float* x     = (const float*)d_in[0];
    const float* ln1w  = (const float*)d_in[1];
    const float* ln1b  = (const float*)d_in[2];
    const float* qkvw  = (const float*)d_in[3];
    const float* qkvb  = (const float*)d_in[4];
    const float* projw = (const float*)d_in[5];
    const float* projb = (const float*)d_in[6];
    const float* ln2w  = (const float*)d_in[7];
    const float* ln2b  = (const float*)d_in[8];
    const float* fc1w  = (const float*)d_in[9];
    const float* fc1b  = (const float*)d_in[10];
    const float* fc2w  = (const float*)d_in[11];
    const float* fc2b  = (const float*)d_in[12];

    float *x2;
    __half *h16, *qkv16, *att16, *mid16, *w16;
    cudaGetSymbolAddress((void**)&x2,    g_x2);
    cudaGetSymbolAddress((void**)&h16,   g_h16);
    cudaGetSymbolAddress((void**)&qkv16, g_qkv16);
    cudaGetSymbolAddress((void**)&att16, g_att16);
    cudaGetSymbolAddress((void**)&mid16, g_mid16);
    cudaGetSymbolAddress((void**)&w16,   g_w16);

    cudaFuncSetAttribute(gemm16<128,0,0,1>, cudaFuncAttributeMaxDynamicSharedMemorySize, DSM_BN128);
    cudaFuncSetAttribute(gemm16<64,0,2,0>,  cudaFuncAttributeMaxDynamicSharedMemorySize, DSM_BN64);
    cudaFuncSetAttribute(gemm16<128,1,0,1>, cudaFuncAttributeMaxDynamicSharedMemorySize, DSM_BN128);
    cudaFuncSetAttribute(gemm16<64,0,1,2>,  cudaFuncAttributeMaxDynamicSharedMemorySize, DSM_BN64);
    cudaFuncSetAttribute(attn_mma, cudaFuncAttributeMaxDynamicSharedMemorySize, ATTN_DSM);

    // 1. weights fp32 -> fp16
    cvt_all<<<1728, 256>>>(qkvw, projw, fc1w, fc2w, w16);
    // 2. fused transpose + LN1: x -> h16
    transln_k<<<dim3(N_/16, B_), 256>>>(x, ln1w, ln1b, h16);
    // 3. QKV projection (fp16 out), BN=128
    gemm16<128,0,0,1><<<dim3(QKVC/128, M_/128), 256, DSM_BN128>>>(
        h16, w16 + W_QKV, qkvb, nullptr, nullptr, nullptr, qkv16, M_, QKVC, C_);
    // 4. attention (fp16 out)
    attn_mma<<<dim3(N_/128, B_*NH), 128, ATTN_DSM>>>(qkv16, att16);
    // 5. proj + residual(x, transposed on the fly) -> x2 fp32, BN=64
    gemm16<64,0,2,0><<<dim3(C_/64, M_/128), 256, DSM_BN64>>>(
        att16, w16 + W_PROJ, projb, nullptr, x, x2, nullptr, M_, C_, C_);
    // 6. LN2 -> fp16
    ln16_k<<<M_, 128>>>(x2, ln2w, ln2b, h16);
    // 7. fc1 + GELU (fp16 out), BN=128
    gemm16<128,1,0,1><<<dim3(HID/128, M_/128), 256, DSM_BN128>>>(
        h16, w16 + W_FC1, fc1b, nullptr, nullptr, nullptr, mid16, M_, HID, C_);
    // 8. fc2 + residual(x2), transposed epilogue -> d_out (B,C,N), BN=64
    gemm16<64,0,1,2><<<dim3(C_/64, M_/128), 256, DSM_BN64>>>(
        mid16, w16 + W_FC2, fc2b, x2, nullptr, (float*)d_out, nullptr, M_, C_, HID);
}

// round 17
// speedup vs baseline: 1.1621x; 1.0581x over previous
#include <cuda_runtime.h>
#include <cuda_fp16.h>
#include <math.h>
#include <stdint.h>

// Problem constants
#define B_   16
#define C_   384
#define N_   1024
#define NH   8
#define HD   48
#define HID  1536
#define M_   (B_*N_)     // 16384 tokens
#define QKVC (3*C_)      // 1152

// ---------------------------------------------------------------------------
// Scratch
// ---------------------------------------------------------------------------
__device__ float  g_x2 [M_*C_];
__device__ __half g_h16 [M_*C_];
__device__ __half g_qkv16[M_*QKVC];
__device__ __half g_att16[M_*C_];
__device__ __half g_mid16[M_*HID];
__device__ __half g_w16[1769472];
#define W_QKV 0
#define W_PROJ 442368
#define W_FC1 589824
#define W_FC2 1179648

// ---------------------------------------------------------------------------
// Helpers
// ---------------------------------------------------------------------------
__device__ __forceinline__ uint32_t smem_u32(const void* p) {
    uint32_t a;
    asm("{ .reg .u64 t; cvta.to.shared.u64 t, %1; cvt.u32.u64 %0, t; }"
        : "=r"(a) : "l"(p));
    return a;
}
#define SW128(o) ((o) ^ (((o) >> 3) & 0x70))

__device__ __forceinline__ void ldsm4(uint32_t addr, uint32_t r[4]) {
    asm volatile("ldmatrix.sync.aligned.m8n8.x4.shared.b16 {%0,%1,%2,%3}, [%4];"
                 : "=r"(r[0]), "=r"(r[1]), "=r"(r[2]), "=r"(r[3]) : "r"(addr));
}
__device__ __forceinline__ void ldsm4t(uint32_t addr, uint32_t r[4]) {
    asm volatile("ldmatrix.sync.aligned.m8n8.x4.trans.shared.b16 {%0,%1,%2,%3}, [%4];"
                 : "=r"(r[0]), "=r"(r[1]), "=r"(r[2]), "=r"(r[3]) : "r"(addr));
}
__device__ __forceinline__ void ldsm2t(uint32_t addr, uint32_t r[2]) {
    asm volatile("ldmatrix.sync.aligned.m8n8.x2.trans.shared.b16 {%0,%1}, [%2];"
                 : "=r"(r[0]), "=r"(r[1]) : "r"(addr));
}
__device__ __forceinline__ void mmaf16(float* c, const uint32_t* a,
                                       uint32_t b0, uint32_t b1) {
    asm volatile("mma.sync.aligned.m16n8k16.row.col.f32.f16.f16.f32 "
                 "{%0,%1,%2,%3}, {%4,%5,%6,%7}, {%8,%9}, {%0,%1,%2,%3};"
                 : "+f"(c[0]), "+f"(c[1]), "+f"(c[2]), "+f"(c[3])
                 : "r"(a[0]), "r"(a[1]), "r"(a[2]), "r"(a[3]), "r"(b0), "r"(b1));
}
__device__ __forceinline__ void mmaf16v(float* c, uint32_t a0, uint32_t a1,
                                        uint32_t a2, uint32_t a3,
                                        uint32_t b0, uint32_t b1) {
    asm volatile("mma.sync.aligned.m16n8k16.row.col.f32.f16.f16.f32 "
                 "{%0,%1,%2,%3}, {%4,%5,%6,%7}, {%8,%9}, {%0,%1,%2,%3};"
                 : "+f"(c[0]), "+f"(c[1]), "+f"(c[2]), "+f"(c[3])
                 : "r"(a0), "r"(a1), "r"(a2), "r"(a3), "r"(b0), "r"(b1));
}
// fp16-accumulator MMA for S = QK^T (output packed f16x2, A-fragment layout)
__device__ __forceinline__ void mmah16(uint32_t* c, const uint32_t* a,
                                       uint32_t b0, uint32_t b1) {
    asm volatile("mma.sync.aligned.m16n8k16.row.col.f16.f16.f16.f16 "
                 "{%0,%1}, {%2,%3,%4,%5}, {%6,%7}, {%0,%1};"
                 : "+r"(c[0]), "+r"(c[1])
                 : "r"(a[0]), "r"(a[1]), "r"(a[2]), "r"(a[3]), "r"(b0), "r"(b1));
}
__device__ __forceinline__ void cpasync16(uint32_t s, const void* g) {
    asm volatile("cp.async.cg.shared.global [%0], [%1], 16;" :: "r"(s), "l"(g));
}
__device__ __forceinline__ uint32_t packh2(float x, float y) {
    __half2 t = __floats2half2_rn(x, y);
    return *(uint32_t*)&t;
}
__device__ __forceinline__ uint32_t h2ex2(uint32_t x) {
    uint32_t r;
    asm("ex2.approx.f16x2 %0, %1;" : "=r"(r) : "r"(x));
    return r;
}
__device__ __forceinline__ uint32_t h2mul(uint32_t a, uint32_t b) {
    uint32_t r;
    asm("mul.f16x2 %0, %1, %2;" : "=r"(r) : "r"(a), "r"(b));
    return r;
}

// ---------------------------------------------------------------------------
// All weights fp32 -> fp16 in one launch
// ---------------------------------------------------------------------------
__global__ void cvt_all(const float* __restrict__ qkvw, const float* __restrict__ projw,
                        const float* __restrict__ fc1w, const float* __restrict__ fc2w,
                        __half* __restrict__ w16) {
    int i = blockIdx.x * 256 + threadIdx.x;   // 0 .. 442367
    const float* s;
    __half* d;
    if (i < 110592)      { s = qkvw;  d = w16 + W_QKV;  }
    else if (i < 147456) { s = projw; d = w16 + W_PROJ; i -= 110592; }
    else if (i < 294912) { s = fc1w;  d = w16 + W_FC1;  i -= 147456; }
    else                 { s = fc2w;  d = w16 + W_FC2;  i -= 294912; }
    float4 v = ((const float4*)s)[i];
    __half2* dp = (__half2*)d;
    dp[2 * i]     = __floats2half2_rn(v.x, v.y);
    dp[2 * i + 1] = __floats2half2_rn(v.z, v.w);
}

// ---------------------------------------------------------------------------
// Fused transpose + LayerNorm: x (B,C,N) fp32 -> h16 (B,N,C) fp16
// ---------------------------------------------------------------------------
__global__ __launch_bounds__(256)
void transln_k(const float* __restrict__ x, const float* __restrict__ w,
               const float* __restrict__ bias, __half* __restrict__ Y) {
    __shared__ float fs[384 * 17];
    __shared__ float ps[256], pq[256];
    __shared__ float mrow[16], rrow[16];
    const int b = blockIdx.y, n0 = blockIdx.x * 16;
    const int tok = threadIdx.x & 15, c0 = threadIdx.x >> 4;
    const float* xb = x + (size_t)b * C_ * N_ + n0;
    float s = 0.0f, q = 0.0f;
    #pragma unroll
    for (int i = 0; i < 24; i++) {
        int c = c0 + i * 16;
        float v = xb[(size_t)c * N_ + tok];
        s += v; q += v * v;
        fs[c * 17 + tok] = v;
    }
    ps[c0 * 16 + tok] = s;
    pq[c0 * 16 + tok] = q;
    __syncthreads();
    if (threadIdx.x < 16) {
        float ss = 0.0f, qq = 0.0f;
        #pragma unroll
        for (int j = 0; j < 16; j++) { ss += ps[j * 16 + threadIdx.x]; qq += pq[j * 16 + threadIdx.x]; }
        float mean = ss * (1.0f / C_);
        float var  = qq * (1.0f / C_) - mean * mean;
        mrow[threadIdx.x] = mean;
        rrow[threadIdx.x] = rsqrtf(var + 1e-5f);
    }
    __syncthreads();
    const int tok2 = threadIdx.x >> 4, part = threadIdx.x & 15;
    const float mean = mrow[tok2], rstd = rrow[tok2];
    __half* yr = Y + (size_t)(b * N_ + n0 + tok2) * C_;
    #pragma unroll
    for (int i = 0; i < 24; i++) {
        int c = part + i * 16;
        float v = fs[c * 17 + tok2];
        yr[c] = __float2half((v - mean) * rstd * w[c] + bias[c]);
    }
}

// ---------------------------------------------------------------------------
// LayerNorm (rows of 384) from token-major fp32, fp16 output (LN2)
// ---------------------------------------------------------------------------
__global__ void ln16_k(const float* __restrict__ X, const float* __restrict__ w,
                       const float* __restrict__ bias, __half* __restrict__ Y) {
    int row = blockIdx.x;
    int tid = threadIdx.x;
    const float* xr = X + (size_t)row * C_;
    float v0 = xr[tid], v1 = xr[tid + 128], v2 = xr[tid + 256];
    float s = v0 + v1 + v2;
    float q = v0 * v0 + v1 * v1 + v2 * v2;
    #pragma unroll
    for (int o = 16; o > 0; o >>= 1) {
        s += __shfl_xor_sync(0xffffffffu, s, o);
        q += __shfl_xor_sync(0xffffffffu, q, o);
    }
    __shared__ float ss[4], sq[4];
    int wid = tid >> 5, lane = tid & 31;
    if (lane == 0) { ss[wid] = s; sq[wid] = q; }
    __syncthreads();
    s = ss[0] + ss[1] + ss[2] + ss[3];
    q = sq[0] + sq[1] + sq[2] + sq[3];
    float mean = s * (1.0f / C_);
    float var  = q * (1.0f / C_) - mean * mean;
    float rstd = rsqrtf(var + 1e-5f);
    __half* yr = Y + (size_t)row * C_;
    yr[tid]       = __float2half((v0 - mean) * rstd * w[tid]       + bias[tid]);
    yr[tid + 128] = __float2half((v1 - mean) * rstd * w[tid + 128] + bias[tid + 128]);
    yr[tid + 256] = __float2half((v2 - mean) * rstd * w[tid + 256] + bias[tid + 256]);
}

// ---------------------------------------------------------------------------
// fp16 mma.sync NT GEMM v2: 128xBN tile (BN = 128 or 64), 256 threads,
// 8 warps (4M x 2N), warp tile 32x(BN/2), k-chunk 64, 2-stage cp.async,
// ONE barrier per chunk, SW128 smem (128B row pitch), ldmatrix.x4.
// ACT: 1 = exact GELU.
// RES: 0 none; 1 fp32 token-major (Res); 2 residual = x (B,C,N) transposed.
// OUT: 0 fp32 token-major; 1 fp16 token-major;
//      2 fp32 transposed to (B,C,N) via smem staging.
// Dynamic smem: 2 stages x (128+BN)*128 bytes.
// ---------------------------------------------------------------------------
template<int BN, int ACT, int RES, int OUT>
__global__ __launch_bounds__(256)
void gemm16(const __half* __restrict__ A, const __half* __restrict__ Bw,
            const float* __restrict__ bias, const float* __restrict__ Res,
            const float* __restrict__ Xres,
            float* __restrict__ Cf, __half* __restrict__ Ch,
            int M, int N, int K) {
    constexpr int STAGE = (128 + BN) * 128;    // bytes per pipeline stage
    constexpr int JT = BN / 16;                // n8 tiles per warp
    constexpr int JP = BN / 32;                // ldsm.x4 B loads per kk
    constexpr int BLD = BN / 32;               // B cp.async iters (256 thr, 8/row)
    extern __shared__ __align__(128) char dsm[];
    const uint32_t base = smem_u32(dsm);
    const int tid = threadIdx.x, lane = tid & 31, warp = tid >> 5;
    const int wm = (warp & 3) * 32, wn = (warp >> 2) * (BN / 2);
    const int m0 = blockIdx.y * 128, n0 = blockIdx.x * BN;
    const int l8 = lane & 7, sub = lane >> 3;
    const int nc = K >> 6;                     // k-chunk 64

    float acc[2][JT][4];
    #pragma unroll
    for (int i = 0; i < 2; i++)
        #pragma unroll
        for (int j = 0; j < JT; j++)
            #pragma unroll
            for (int c = 0; c < 4; c++) acc[i][j][c] = 0.0f;

    // A: 128 rows x 128B (8 x 16B per row) -> 4 iters; B: BN rows -> BLD iters
    #define ISSUE(st, k0)                                                        \
        do {                                                                     \
            _Pragma("unroll")                                                    \
            for (int t = 0; t < 4; t++) {                                        \
                int e = tid + t * 256;                                           \
                int r = e >> 3, cc = e & 7;                                      \
                cpasync16(base + (st) * STAGE + SW128((uint32_t)(r * 128 + cc * 16)), \
                          A + (size_t)(m0 + r) * K + (k0) + cc * 8);             \
            }                                                                    \
            _Pragma("unroll")                                                    \
            for (int t = 0; t < BLD; t++) {                                      \
                int e = tid + t * 256;                                           \
                int r = e >> 3, cc = e & 7;                                      \
                cpasync16(base + (st) * STAGE + 16384 + SW128((uint32_t)(r * 128 + cc * 16)), \
                          Bw + (size_t)(n0 + r) * K + (k0) + cc * 8);            \
            }                                                                    \
            asm volatile("cp.async.commit_group;");                              \
        } while (0)

    ISSUE(0, 0);

    for (int c = 0; c < nc; c++) {
        const int buf = c & 1;
        asm volatile("cp.async.wait_group 0;");
        __syncthreads();   // also orders prior compute's reads of buf^1
        if (c + 1 < nc) ISSUE(buf ^ 1, (c + 1) * 64);

        const uint32_t aA = base + buf * STAGE;
        const uint32_t aB = aA + 16384;
        #pragma unroll
        for (int kk = 0; kk < 4; kk++) {
            uint32_t af[2][4];
            #pragma unroll
            for (int i = 0; i < 2; i++) {
                uint32_t off = (uint32_t)((wm + i * 16 + (sub & 1) * 8 + l8) * 128
                                          + kk * 32 + (sub >> 1) * 16);
                ldsm4(aA + SW128(off), af[i]);
            }
            #pragma unroll
            for (int jp = 0; jp < JP; jp++) {
                uint32_t bf[4];
                uint32_t off = (uint32_t)((wn + jp * 16 + (sub & 1) * 8 + l8) * 128
                                          + kk * 32 + (sub >> 1) * 16);
                ldsm4(aB + SW128(off), bf);
                #pragma unroll
                for (int i = 0; i < 2; i++) {
                    mmaf16(acc[i][2 * jp],     af[i], bf[0], bf[2]);
                    mmaf16(acc[i][2 * jp + 1], af[i], bf[1], bf[3]);
                }
            }
        }
        // no trailing sync: next iteration's leading sync orders these reads
        // before ISSUE overwrites buf^1... (ISSUE targets buf^1 which was
        // last read in iteration c-1, already ordered by this iteration's
        // leading __syncthreads).
    }
    #undef ISSUE

    const int rq = lane >> 2, cq = (lane & 3) * 2;

    if (OUT == 2) {
        float* stage = (float*)dsm;
        const int bb = m0 >> 10;
        const int nbase = m0 & 1023;
        if (BN == 128) {
            #pragma unroll 1
            for (int halfc = 0; halfc < 2; halfc++) {
                __syncthreads();
                if ((warp >> 2) == halfc) {
                    #pragma unroll
                    for (int i = 0; i < 2; i++)
                        #pragma unroll
                        for (int hrow = 0; hrow < 2; hrow++) {
                            int row_local = wm + i * 16 + rq + hrow * 8;
                            #pragma unroll
                            for (int j = 0; j < JT; j++) {
                                int col_local = j * 8 + cq;
                                int col = n0 + halfc * 64 + col_local;
                                float v0 = acc[i][j][hrow * 2 + 0] + bias[col];
                                float v1 = acc[i][j][hrow * 2 + 1] + bias[col + 1];
                                if (RES == 1) {
                                    float2 r = *(const float2*)&Res[(size_t)(m0 + row_local) * N + col];
                                    v0 += r.x; v1 += r.y;
                                }
                                stage[row_local * 65 + col_local]     = v0;
                                stage[row_local * 65 + col_local + 1] = v1;
                            }
                        }
                }
                __syncthreads();
                #pragma unroll
                for (int it = 0; it < 32; it++) {
                    int idx = tid + it * 256;
                    int cl = idx >> 7, nl = idx & 127;
                    Cf[((size_t)bb * C_ + n0 + halfc * 64 + cl) * N_ + nbase + nl]
                        = stage[nl * 65 + cl];
                }
            }
        } else {
            __syncthreads();
            #pragma unroll
            for (int i = 0; i < 2; i++)
                #pragma unroll
                for (int hrow = 0; hrow < 2; hrow++) {
                    int row_local = wm + i * 16 + rq + hrow * 8;
                    #pragma unroll
                    for (int j = 0; j < JT; j++) {
                        int col_local = wn + j * 8 + cq;
                        int col = n0 + col_local;
                        float v0 = acc[i][j][hrow * 2 + 0] + bias[col];
                        float v1 = acc[i][j][hrow * 2 + 1] + bias[col + 1];
                        if (RES == 1) {
                            float2 r = *(const float2*)&Res[(size_t)(m0 + row_local) * N + col];
                            v0 += r.x; v1 += r.y;
                        }
                        stage[row_local * 65 + col_local]     = v0;
                        stage[row_local * 65 + col_local + 1] = v1;
                    }
                }
            __syncthreads();
            #pragma unroll
            for (int it = 0; it < 32; it++) {
                int idx = tid + it * 256;
                int cl = idx >> 7, nl = idx & 127;
                Cf[((size_t)bb * C_ + n0 + cl) * N_ + nbase + nl]
                    = stage[nl * 65 + cl];
            }
        }
        return;
    }

    #pragma unroll
    for (int i = 0; i < 2; i++) {
        #pragma unroll
        for (int half = 0; half < 2; half++) {
            int row = m0 + wm + i * 16 + rq + half * 8;
            #pragma unroll
            for (int j = 0; j < JT; j++) {
                int col = n0 + wn + j * 8 + cq;
                size_t off = (size_t)row * N + col;
                float v0 = acc[i][j][half * 2 + 0] + bias[col];
                float v1 = acc[i][j][half * 2 + 1] + bias[col + 1];
                if (ACT == 1) {
                    v0 = 0.5f * v0 * (1.0f + erff(v0 * 0.70710678118654752f));
                    v1 = 0.5f * v1 * (1.0f + erff(v1 * 0.70710678118654752f));
                }
                if (RES == 1) {
                    float2 r = *(const float2*)&Res[off];
                    v0 += r.x; v1 += r.y;
                }
                if (RES == 2) {
                    int bb = row >> 10, nn = row & 1023;
                    v0 += Xres[((size_t)bb * C_ + col)     * N_ + nn];
                    v1 += Xres[((size_t)bb * C_ + col + 1) * N_ + nn];
                }
                if (OUT == 1) {
                    *(__half2*)&Ch[off] = __floats2half2_rn(v0, v1);
                } else {
                    *(float2*)&Cf[off] = make_float2(v0, v1);
                }
            }
        }
    }
}

// ---------------------------------------------------------------------------
// Tensor-core flash attention — unchanged from R16 (proven).
// fp16 S-accumulators, pitch-112 smem, 3 CTAs/SM.
// dsm: Q@0 (14336) | K0@14336 | V0@28672 | K1@43008 | V1@57344  (71680)
// ---------------------------------------------------------------------------
#define PITCH 112
#define ATTN_DSM 71680
__global__ __launch_bounds__(128, 3)
void attn_mma(const __half* __restrict__ qkv16, __half* __restrict__ att16) {
    extern __shared__ __align__(128) char dsm[];
    const uint32_t base = smem_u32(dsm);
    const int tid = threadIdx.x, lane = tid & 31, warp = tid >> 5;
    const int bh = blockIdx.y, b = bh >> 3, h = bh & 7;
    const int tok0 = b * N_ + blockIdx.x * 128;
    const float kscale = 0.14433756729740643f * 1.4426950408889634f;  // scale*log2e
    const int l8 = lane & 7, sub = lane >> 3;
    const int wm = warp * 32;

    // Q tile (pitch 112)
    {
        const uint4* src = (const uint4*)(qkv16 + (size_t)(tok0 + tid) * QKVC + h * HD);
        #pragma unroll
        for (int j = 0; j < 6; j++)
            *(uint4*)(dsm + tid * PITCH + j * 16) = src[j];
    }
    // ones column (col 48 = 1.0h, cols 49..55 = 0) in both V buffers
    #pragma unroll
    for (int bufi = 0; bufi < 2; bufi++) {
        char* vb = dsm + 28672 + bufi * 28672;
        *(uint4*)(vb + tid * PITCH + 96) = make_uint4(0x3C00u, 0, 0, 0);
    }

    #define ISSUE_KV(bufi, kt)                                                   \
        do {                                                                     \
            int tk = b * N_ + (kt) * 128 + tid;                                  \
            const __half* kp = qkv16 + (size_t)tk * QKVC + C_     + h * HD;      \
            const __half* vp = qkv16 + (size_t)tk * QKVC + 2 * C_ + h * HD;      \
            uint32_t kb = base + 14336 + (bufi) * 28672;                         \
            _Pragma("unroll")                                                    \
            for (int j = 0; j < 6; j++) {                                        \
                cpasync16(kb + tid * PITCH + j * 16,         kp + j * 8);        \
                cpasync16(kb + 14336 + tid * PITCH + j * 16, vp + j * 8);        \
            }                                                                    \
            asm volatile("cp.async.commit_group;");                              \
        } while (0)

    ISSUE_KV(0, 0);
    __syncthreads();   // Q + ones visible

    // Q fragments, pre-scaled by kscale (fp16)
    const uint32_t ksc2 = packh2(kscale, kscale);
    uint32_t qa[2][3][4];
    #pragma unroll
    for (int i = 0; i < 2; i++)
        #pragma unroll
        for (int ks = 0; ks < 3; ks++) {
            uint32_t off = (uint32_t)((wm + i * 16 + (sub & 1) * 8 + l8) * PITCH
                                      + ks * 32 + (sub >> 1) * 16);
            ldsm4(base + off, qa[i][ks]);
            #pragma unroll
            for (int q = 0; q < 4; q++) qa[i][ks][q] = h2mul(qa[i][ks][q], ksc2);
        }

    float o[2][7][4];
    #pragma unroll
    for (int i = 0; i < 2; i++)
        #pragma unroll
        for (int j = 0; j < 7; j++)
            #pragma unroll
            for (int c = 0; c < 4; c++) o[i][j][c] = 0.0f;

    for (int kt = 0; kt < 8; kt++) {
        const int buf = kt & 1;
        if (kt + 1 < 8) {
            ISSUE_KV(buf ^ 1, kt + 1);
            asm volatile("cp.async.wait_group 1;");
        } else {
            asm volatile("cp.async.wait_group 0;");
        }
        __syncthreads();

        const uint32_t aK = base + 14336 + buf * 28672;
        const uint32_t aV = aK + 14336;

        #pragma unroll
        for (int kh = 0; kh < 2; kh++) {
            uint32_t s16[2][8][2];
            #pragma unroll
            for (int i = 0; i < 2; i++)
                #pragma unroll
                for (int j = 0; j < 8; j++) { s16[i][j][0] = 0u; s16[i][j][1] = 0u; }

            #pragma unroll
            for (int ks = 0; ks < 3; ks++) {
                #pragma unroll
                for (int jp = 0; jp < 4; jp++) {
                    uint32_t bf[4];
                    uint32_t off = (uint32_t)((kh * 64 + jp * 16 + (sub & 1) * 8 + l8) * PITCH
                                              + ks * 32 + (sub >> 1) * 16);
                    ldsm4(aK + off, bf);
                    #pragma unroll
                    for (int i = 0; i < 2; i++) {
                        mmah16(s16[i][2 * jp],     qa[i][ks], bf[0], bf[2]);
                        mmah16(s16[i][2 * jp + 1], qa[i][ks], bf[1], bf[3]);
                    }
                }
            }

            #pragma unroll
            for (int i = 0; i < 2; i++)
                #pragma unroll
                for (int j = 0; j < 8; j++) {
                    s16[i][j][0] = h2ex2(s16[i][j][0]);
                    s16[i][j][1] = h2ex2(s16[i][j][1]);
                }

            #pragma unroll
            for (int t = 0; t < 4; t++) {
                uint32_t vrow = (uint32_t)((kh * 64 + t * 16 + (sub & 1) * 8 + l8) * PITCH);
                uint32_t vb3[3][4];
                #pragma unroll
                for (int jdp = 0; jdp < 3; jdp++)
                    ldsm4t(aV + vrow + jdp * 32 + (sub >> 1) * 16, vb3[jdp]);
                uint32_t vo[2];
                ldsm2t(aV + vrow + 96, vo);
                #pragma unroll
                for (int i = 0; i < 2; i++) {
                    uint32_t a0 = s16[i][2 * t][0],     a1 = s16[i][2 * t][1];
                    uint32_t a2 = s16[i][2 * t + 1][0], a3 = s16[i][2 * t + 1][1];
                    #pragma unroll
                    for (int jdp = 0; jdp < 3; jdp++) {
                        mmaf16v(o[i][2 * jdp],     a0, a1, a2, a3, vb3[jdp][0], vb3[jdp][1]);
                        mmaf16v(o[i][2 * jdp + 1], a0, a1, a2, a3, vb3[jdp][2], vb3[jdp][3]);
                    }
                    mmaf16v(o[i][6], a0, a1, a2, a3, vo[0], vo[1]);
                }
            }
        }
        __syncthreads();
    }
    #undef ISSUE_KV

    const int rq = lane >> 2, cq = (lane & 3) * 2;
    #pragma unroll
    for (int i = 0; i < 2; i++) {
        float l0 = __shfl_sync(0xffffffffu, o[i][6][0], lane & 0x1c);
        float l1 = __shfl_sync(0xffffffffu, o[i][6][2], lane & 0x1c);
        float inv0 = 1.0f / l0, inv1 = 1.0f / l1;
        int r0 = tok0 + wm + i * 16 + rq;
        #pragma unroll
        for (int j = 0; j < 6; j++) {
            int col = h * HD + j * 8 + cq;
            *(__half2*)&att16[(size_t)r0 * C_ + col] =
                __floats2half2_rn(o[i][j][0] * inv0, o[i][j][1] * inv0);
            *(__half2*)&att16[(size_t)(r0 + 8) * C_ + col] =
                __floats2half2_rn(o[i][j][2] * inv1, o[i][j][3] * inv1);
        }
    }
}

// ---------------------------------------------------------------------------
// Launch
// ---------------------------------------------------------------------------
#define DSM_BN128 65536   // 2 stages x 32KB
#define DSM_BN64  49152   // 2 stages x 24KB (>= 128x65x4 = 33.3KB OUT=2 stage)

extern "C" void kernel_launch(void* const* d_in, const int* in_sizes, int n_in,
                              void* d_out, int out_size) {
    const float* x     = (const float*)d_in[0];
    const float* ln1w  = (const float*)d_in[1];
    const float* ln1b  = (const float*)d_in[2];
    const float* qkvw  = (const float*)d_in[3];
    const float* qkvb  = (const float*)d_in[4];
    const float* projw = (const float*)d_in[5];
    const float* projb = (const float*)d_in[6];
    const float* ln2w  = (const float*)d_in[7];
    const float* ln2b  = (const float*)d_in[8];
    const float* fc1w  = (const float*)d_in[9];
    const float* fc1b  = (const float*)d_in[10];
    const float* fc2w  = (const float*)d_in[11];
    const float* fc2b  = (const float*)d_in[12];

    float *x2;
    __half *h16, *qkv16, *att16, *mid16, *w16;
    cudaGetSymbolAddress((void**)&x2,    g_x2);
    cudaGetSymbolAddress((void**)&h16,   g_h16);
    cudaGetSymbolAddress((void**)&qkv16, g_qkv16);
    cudaGetSymbolAddress((void**)&att16, g_att16);
    cudaGetSymbolAddress((void**)&mid16, g_mid16);
    cudaGetSymbolAddress((void**)&w16,   g_w16);

    cudaFuncSetAttribute(gemm16<128,0,0,1>, cudaFuncAttributeMaxDynamicSharedMemorySize, DSM_BN128);
    cudaFuncSetAttribute(gemm16<64,0,2,0>,  cudaFuncAttributeMaxDynamicSharedMemorySize, DSM_BN64);
    cudaFuncSetAttribute(gemm16<128,1,0,1>, cudaFuncAttributeMaxDynamicSharedMemorySize, DSM_BN128);
    cudaFuncSetAttribute(gemm16<64,0,1,2>,  cudaFuncAttributeMaxDynamicSharedMemorySize, DSM_BN64);
    cudaFuncSetAttribute(attn_mma, cudaFuncAttributeMaxDynamicSharedMemorySize, ATTN_DSM);

    // 1. weights fp32 -> fp16
    cvt_all<<<1728, 256>>>(qkvw, projw, fc1w, fc2w, w16);
    // 2. fused transpose + LN1: x -> h16
    transln_k<<<dim3(N_/16, B_), 256>>>(x, ln1w, ln1b, h16);
    // 3. QKV projection (fp16 out), BN=128
    gemm16<128,0,0,1><<<dim3(QKVC/128, M_/128), 256, DSM_BN128>>>(
        h16, w16 + W_QKV, qkvb, nullptr, nullptr, nullptr, qkv16, M_, QKVC, C_);
    // 4. attention (fp16 out)
    attn_mma<<<dim3(N_/128, B_*NH), 128, ATTN_DSM>>>(qkv16, att16);
    // 5. proj + residual(x, transposed on the fly) -> x2 fp32, BN=64
    gemm16<64,0,2,0><<<dim3(C_/64, M_/128), 256, DSM_BN64>>>(
        att16, w16 + W_PROJ, projb, nullptr, x, x2, nullptr, M_, C_, C_);
    // 6. LN2 -> fp16
    ln16_k<<<M_, 128>>>(x2, ln2w, ln2b, h16);
    // 7. fc1 + GELU (fp16 out), BN=128
    gemm16<128,1,0,1><<<dim3(HID/128, M_/128), 256, DSM_BN128>>>(
        h16, w16 + W_FC1, fc1b, nullptr, nullptr, nullptr, mid16, M_, HID, C_);
    // 8. fc2 + residual(x2), transposed epilogue -> d_out (B,C,N), BN=64
    gemm16<64,0,1,2><<<dim3(C_/64, M_/128), 256, DSM_BN64>>>(
        mid16, w16 + W_FC2, fc2b, x2, nullptr, (float*)d_out, nullptr, M_, C_, HID);
}